// round 12
// baseline (speedup 1.0000x reference)
#include <cuda_runtime.h>
#include <cstdint>

namespace {
using u64 = unsigned long long;

__device__ __forceinline__ u64 pk(float x) {
  u64 d; unsigned xi = __float_as_uint(x);
  asm("mov.b64 %0, {%1, %1};" : "=l"(d) : "r"(xi));
  return d;
}
__device__ __forceinline__ u64 ffma2(u64 a, u64 b, u64 c) {
  u64 d;
  asm("fma.rn.f32x2 %0, %1, %2, %3;" : "=l"(d) : "l"(a), "l"(b), "l"(c));
  return d;
}
__device__ __forceinline__ float2 unpk(u64 d) {
  unsigned lo, hi;
  asm("mov.b64 {%0, %1}, %2;" : "=r"(lo), "=r"(hi) : "l"(d));
  return make_float2(__uint_as_float(lo), __uint_as_float(hi));
}
__device__ __forceinline__ uint32_t cvt_tf32(float x) {
  uint32_t r;
  asm("cvt.rna.tf32.f32 %0, %1;" : "=r"(r) : "f"(x));
  return r;
}
__device__ __forceinline__ void mma_tf32(float d[4], const uint32_t a[4],
                                         uint32_t b0, uint32_t b1) {
  asm volatile(
      "mma.sync.aligned.m16n8k8.row.col.f32.tf32.tf32.f32 "
      "{%0,%1,%2,%3}, {%4,%5,%6,%7}, {%8,%9}, {%0,%1,%2,%3};"
      : "+f"(d[0]), "+f"(d[1]), "+f"(d[2]), "+f"(d[3])
      : "r"(a[0]), "r"(a[1]), "r"(a[2]), "r"(a[3]), "r"(b0), "r"(b1));
}

struct P {
  const float *feat0, *feat1, *edge_inv;
  const int *src, *dst;
  const float *b00, *b01, *b10, *b11;
  const float *w1[4], *bb1[4], *w2[4], *bb2[4], *w3[4];  // 00,01,10,11
  float* out;
  int E;
};

// pair11 W3 reordered f-major: [f][m][c*16+k]
__device__ float g_W3T11[24576];

__global__ void prolog(const float* __restrict__ w3_11, float* out, int nout) {
  int i = blockIdx.x * 256 + threadIdx.x;
  if (i < nout) out[i] = 0.f;
  if (i < 24576) {
    int f = i >> 13;
    int r = i & 8191;
    int m = r >> 8;
    int n = r & 255;
    int c = n >> 4, k = n & 15;
    g_W3T11[i] = w3_11[m*768 + c*48 + k*3 + f];
  }
}

// smem float offsets
constexpr int S_F0  = 0;        // [128][16]  f0; reused as t1 before pair10
constexpr int S_F1  = 2048;     // [128][48]
constexpr int S_EB  = 8192;     // [128][10]
constexpr int S_B11 = 9472;     // [128][27]
constexpr int S_H2  = 12928;    // [128][36]  (padded rows, conflict-free A frags)
constexpr int S_W3  = 17536;    // [32][260]  (padded rows, conflict-free B frags)
constexpr int S_MLPA= 25856;    // 1152
constexpr int S_MLPB= 27008;    // 1152
constexpr int S_TOT = 28160;    // 112640 B (x2 CTA = 225 KB)

__device__ __forceinline__ void radial_half(const float* __restrict__ mlp,
                                            float ei0, float ei1, int mhalf,
                                            float h2[16]) {
  const float* w1 = mlp; const float* b1 = mlp + 64;
  const float* w2 = mlp + 96; const float* b2 = mlp + 1120;
  float h1[32];
#pragma unroll
  for (int j = 0; j < 32; j++)
    h1[j] = fmaxf(fmaf(ei0, w1[j], fmaf(ei1, w1[32 + j], b1[j])), 0.f);
  u64 acc[8];
  const u64* b2p = reinterpret_cast<const u64*>(b2 + mhalf);
#pragma unroll
  for (int j = 0; j < 8; j++) acc[j] = b2p[j];
#pragma unroll
  for (int n = 0; n < 32; n++) {
    u64 h = pk(h1[n]);
    const u64* wrow = reinterpret_cast<const u64*>(w2 + n*32 + mhalf);
#pragma unroll
    for (int j = 0; j < 8; j++) acc[j] = ffma2(h, wrow[j], acc[j]);
  }
#pragma unroll
  for (int j = 0; j < 8; j++) {
    float2 q = unpk(acc[j]);
    h2[2*j]   = fmaxf(q.x, 0.f);
    h2[2*j+1] = fmaxf(q.y, 0.f);
  }
}

// Guard-free main kernel: every block covers 128 valid edges.
__global__ void __launch_bounds__(256, 2) convFused(P p) {
  extern __shared__ float sm[];
  int t = threadIdx.x;
  int eb = blockIdx.x * 128;
  int w = t >> 5, lane = t & 31;
  int r = lane >> 2, q = lane & 3;
  int el0 = w*16 + r, el1 = el0 + 8;
  int el2 = t >> 1, mhalf = (t & 1) * 16;

  // ---------- stage per-edge data ----------
  if (t < 128) {
    int e = eb + t;
    float* EB = sm + S_EB + t*10;
    EB[0] = p.edge_inv[2*e];
    EB[1] = p.edge_inv[2*e+1];
    EB[2] = p.b00[e];
    EB[3] = p.b01[3*e]; EB[4] = p.b01[3*e+1]; EB[5] = p.b01[3*e+2];
    EB[6] = p.b10[3*e]; EB[7] = p.b10[3*e+1]; EB[8] = p.b10[3*e+2];
    reinterpret_cast<int*>(EB)[9] = p.dst[e];
  }
  {
    int half = t & 1;
    int e = eb + el2;
    int s = p.src[e];
    const float4* f0g = reinterpret_cast<const float4*>(p.feat0 + (size_t)s*16);
    float4* f0s = reinterpret_cast<float4*>(sm + S_F0 + el2*16);
    f0s[half*2+0] = f0g[half*2+0];
    f0s[half*2+1] = f0g[half*2+1];
    const float4* f1g = reinterpret_cast<const float4*>(p.feat1 + (size_t)s*48);
    float4* f1s = reinterpret_cast<float4*>(sm + S_F1 + el2*48);
#pragma unroll
    for (int qq = 0; qq < 6; qq++) f1s[half*6+qq] = f1g[half*6+qq];
    const float* bg = p.b11 + (size_t)e*27;
    float* bs = sm + S_B11 + el2*27;
    for (int qq = half; qq < 27; qq += 2) bs[qq] = bg[qq];
  }

  auto stage_mlp = [&](int pr, int off) {
    float* d = sm + off;
    if (t < 64) d[t] = p.w1[pr][t];
    else if (t < 96) d[64 + (t-64)] = p.bb1[pr][t-64];
    else if (t < 128) d[1120 + (t-96)] = p.bb2[pr][t-96];
    for (int i = t; i < 1024; i += 256) d[96 + i] = p.w2[pr][i];
  };
  auto do_radial = [&](int off, bool fold) {
    const float* EB = sm + S_EB + el2*10;
    float h2[16];
    radial_half(sm + off, EB[0], EB[1], mhalf, h2);
    float sc = fold ? EB[2] : 1.f;
#pragma unroll
    for (int j = 0; j < 16; j++)
      sm[S_H2 + el2*36 + mhalf + j] = h2[j] * sc;
  };
  auto w3load = [&](const float* __restrict__ g, float4 rr[8]) {
    const float4* s4 = reinterpret_cast<const float4*>(g);
#pragma unroll
    for (int qq = 0; qq < 8; qq++) rr[qq] = s4[t + 256*qq];
  };
  auto w3store = [&](const float4 rr[8]) {
#pragma unroll
    for (int qq = 0; qq < 8; qq++) {
      int i4 = t + 256*qq;
      int row = i4 >> 6, col4 = (i4 & 63) * 4;
      *reinterpret_cast<float4*>(sm + S_W3 + row*260 + col4) = rr[qq];
    }
  };
  auto loadA = [&](uint32_t A[4][4]) {
#pragma unroll
    for (int kt = 0; kt < 4; kt++) {
      A[kt][0] = cvt_tf32(sm[S_H2 + el0*36 + kt*8 + q]);
      A[kt][1] = cvt_tf32(sm[S_H2 + el1*36 + kt*8 + q]);
      A[kt][2] = cvt_tf32(sm[S_H2 + el0*36 + kt*8 + q + 4]);
      A[kt][3] = cvt_tf32(sm[S_H2 + el1*36 + kt*8 + q + 4]);
    }
  };
  auto mma_slice = [&](const uint32_t A[4][4], int ns, float D[8][4]) {
#pragma unroll
    for (int i = 0; i < 8; i++)
#pragma unroll
      for (int j = 0; j < 4; j++) D[i][j] = 0.f;
#pragma unroll
    for (int nt8 = 0; nt8 < 8; nt8++) {
      int n0 = (ns*8 + nt8)*8 + r;
#pragma unroll
      for (int kt = 0; kt < 4; kt++) {
        uint32_t b0 = cvt_tf32(sm[S_W3 + (kt*8 + q)*260 + n0]);
        uint32_t b1 = cvt_tf32(sm[S_W3 + (kt*8 + q + 4)*260 + n0]);
        mma_tf32(D[nt8], A[kt], b0, b1);
      }
    }
  };

  // vec-dot epilogue (pairs 00/01/10): vec in S_F0; mode 0 -> deg0, 1 -> deg1*b01
  auto chunk_vec = [&](int mode) {
    uint32_t A[4][4];
    loadA(A);
    float fa0 = sm[S_F0 + el0*16 + 2*q],     fa1 = sm[S_F0 + el0*16 + 2*q + 1];
    float fa2 = sm[S_F0 + el0*16 + 2*q + 8], fa3 = sm[S_F0 + el0*16 + 2*q + 9];
    float fb0 = sm[S_F0 + el1*16 + 2*q],     fb1 = sm[S_F0 + el1*16 + 2*q + 1];
    float fb2 = sm[S_F0 + el1*16 + 2*q + 8], fb3 = sm[S_F0 + el1*16 + 2*q + 9];
#pragma unroll 1
    for (int ns = 0; ns < 4; ns++) {
      float D[8][4];
      mma_slice(A, ns, D);
#pragma unroll
      for (int cc = 0; cc < 4; cc++) {
        int c = ns*4 + cc;
        float v0 = D[cc*2][0]*fa0 + D[cc*2][1]*fa1 + D[cc*2+1][0]*fa2 + D[cc*2+1][1]*fa3;
        float v1 = D[cc*2][2]*fb0 + D[cc*2][3]*fb1 + D[cc*2+1][2]*fb2 + D[cc*2+1][3]*fb3;
        v0 += __shfl_xor_sync(0xffffffffu, v0, 1);
        v0 += __shfl_xor_sync(0xffffffffu, v0, 2);
        v1 += __shfl_xor_sync(0xffffffffu, v1, 1);
        v1 += __shfl_xor_sync(0xffffffffu, v1, 2);
        if (q == 0) {
          const float* E0 = sm + S_EB + el0*10;
          const float* E1 = sm + S_EB + el1*10;
          int d0 = reinterpret_cast<const int*>(E0)[9];
          int d1 = reinterpret_cast<const int*>(E1)[9];
          if (mode == 0) {
            atomicAdd(p.out + (size_t)d0*64 + c*4, v0);
            atomicAdd(p.out + (size_t)d1*64 + c*4, v1);
          } else {
            float* o0 = p.out + (size_t)d0*64 + c*4;
            float* o1 = p.out + (size_t)d1*64 + c*4;
            atomicAdd(o0 + 1, v0*E0[3]); atomicAdd(o0 + 2, v0*E0[4]); atomicAdd(o0 + 3, v0*E0[5]);
            atomicAdd(o1 + 1, v1*E1[3]); atomicAdd(o1 + 2, v1*E1[4]); atomicAdd(o1 + 3, v1*E1[5]);
          }
        }
      }
    }
  };

  float4 wreg[8];

  stage_mlp(0, S_MLPA);
  __syncthreads();

  // ---- chunk 0: pair00 (b00 folded) -> deg0 ----
  w3load(p.w3[0], wreg);
  do_radial(S_MLPA, true);
  w3store(wreg);
  __syncthreads();
  chunk_vec(0);
  stage_mlp(1, S_MLPB);
  w3load(p.w3[1], wreg);
  __syncthreads();

  // ---- chunk 1: pair01 -> deg1 (x b01) ----
  do_radial(S_MLPB, false);
  w3store(wreg);
  __syncthreads();
  chunk_vec(1);
  stage_mlp(2, S_MLPA);
  w3load(p.w3[2], wreg);
  __syncthreads();

  // ---- chunk 2: pair10 -> deg0; t1 precomputed into S_F0 ----
  do_radial(S_MLPA, false);
  {
    int half = t & 1, kh = half*8;
    const float* EB = sm + S_EB + el2*10;
    float g0 = EB[6], g1 = EB[7], g2 = EB[8];
    const float* f1 = sm + S_F1 + el2*48 + kh*3;
    float* t1 = sm + S_F0 + el2*16 + kh;
#pragma unroll
    for (int j = 0; j < 8; j++)
      t1[j] = f1[j*3]*g0 + f1[j*3+1]*g1 + f1[j*3+2]*g2;
  }
  w3store(wreg);
  __syncthreads();
  chunk_vec(0);
  stage_mlp(3, S_MLPB);
  w3load(g_W3T11, wreg);
  __syncthreads();

  // ---- chunks 3..5: pair11 (f = 0,1,2) -> deg1 ----
  do_radial(S_MLPB, false);
  w3store(wreg);
  __syncthreads();
  {
    uint32_t A[4][4];
    loadA(A);
    // f1 values for this lane's 4 kf slots x 3 components x 2 edges
    float ga[4][3], gb[4][3];
    int kfs[4] = {2*q, 2*q + 1, 2*q + 8, 2*q + 9};
#pragma unroll
    for (int s2 = 0; s2 < 4; s2++)
#pragma unroll
      for (int i = 0; i < 3; i++) {
        ga[s2][i] = sm[S_F1 + el0*48 + kfs[s2]*3 + i];
        gb[s2][i] = sm[S_F1 + el1*48 + kfs[s2]*3 + i];
      }
#pragma unroll 1
    for (int f = 0; f < 3; f++) {
#pragma unroll 1
      for (int ns = 0; ns < 4; ns++) {
        float D[8][4];
        mma_slice(A, ns, D);
#pragma unroll
        for (int cc = 0; cc < 4; cc++) {
          int c = ns*4 + cc;
          float s0a = D[cc*2][0]*ga[0][0] + D[cc*2][1]*ga[1][0] + D[cc*2+1][0]*ga[2][0] + D[cc*2+1][1]*ga[3][0];
          float s1a = D[cc*2][0]*ga[0][1] + D[cc*2][1]*ga[1][1] + D[cc*2+1][0]*ga[2][1] + D[cc*2+1][1]*ga[3][1];
          float s2a = D[cc*2][0]*ga[0][2] + D[cc*2][1]*ga[1][2] + D[cc*2+1][0]*ga[2][2] + D[cc*2+1][1]*ga[3][2];
          float s0b = D[cc*2][2]*gb[0][0] + D[cc*2][3]*gb[1][0] + D[cc*2+1][2]*gb[2][0] + D[cc*2+1][3]*gb[3][0];
          float s1b = D[cc*2][2]*gb[0][1] + D[cc*2][3]*gb[1][1] + D[cc*2+1][2]*gb[2][1] + D[cc*2+1][3]*gb[3][1];
          float s2b = D[cc*2][2]*gb[0][2] + D[cc*2][3]*gb[1][2] + D[cc*2+1][2]*gb[2][2] + D[cc*2+1][3]*gb[3][2];
          s0a += __shfl_xor_sync(0xffffffffu, s0a, 1); s0a += __shfl_xor_sync(0xffffffffu, s0a, 2);
          s1a += __shfl_xor_sync(0xffffffffu, s1a, 1); s1a += __shfl_xor_sync(0xffffffffu, s1a, 2);
          s2a += __shfl_xor_sync(0xffffffffu, s2a, 1); s2a += __shfl_xor_sync(0xffffffffu, s2a, 2);
          s0b += __shfl_xor_sync(0xffffffffu, s0b, 1); s0b += __shfl_xor_sync(0xffffffffu, s0b, 2);
          s1b += __shfl_xor_sync(0xffffffffu, s1b, 1); s1b += __shfl_xor_sync(0xffffffffu, s1b, 2);
          s2b += __shfl_xor_sync(0xffffffffu, s2b, 1); s2b += __shfl_xor_sync(0xffffffffu, s2b, 2);
          if (q == 0) {
            const float* Ba = sm + S_B11 + el0*27 + f*3;   // B[i*9 + f*3 + o]
            const float* Bb = sm + S_B11 + el1*27 + f*3;
            int d0 = reinterpret_cast<const int*>(sm + S_EB + el0*10)[9];
            int d1 = reinterpret_cast<const int*>(sm + S_EB + el1*10)[9];
            float* oa = p.out + (size_t)d0*64 + c*4;
            float* ob = p.out + (size_t)d1*64 + c*4;
            atomicAdd(oa + 1, s0a*Ba[0] + s1a*Ba[9]  + s2a*Ba[18]);
            atomicAdd(oa + 2, s0a*Ba[1] + s1a*Ba[10] + s2a*Ba[19]);
            atomicAdd(oa + 3, s0a*Ba[2] + s1a*Ba[11] + s2a*Ba[20]);
            atomicAdd(ob + 1, s0b*Bb[0] + s1b*Bb[9]  + s2b*Bb[18]);
            atomicAdd(ob + 2, s0b*Bb[1] + s1b*Bb[10] + s2b*Bb[19]);
            atomicAdd(ob + 3, s0b*Bb[2] + s1b*Bb[11] + s2b*Bb[20]);
          }
        }
      }
      if (f < 2) {
        w3load(g_W3T11 + (f+1)*8192, wreg);
        __syncthreads();
        w3store(wreg);
        __syncthreads();
      }
    }
  }
}

// ---------- scalar tail (E % 128 edges; weights from gmem) ----------
__device__ void radial_g(const float* w1, const float* b1, const float* w2,
                         const float* b2, float ei0, float ei1, float h2[32]) {
  float h1[32];
  for (int m = 0; m < 32; m++)
    h1[m] = fmaxf(fmaf(ei0, w1[m], fmaf(ei1, w1[32+m], b1[m])), 0.f);
  for (int m = 0; m < 32; m++) {
    float a = b2[m];
    for (int n = 0; n < 32; n++) a = fmaf(h1[n], w2[n*32 + m], a);
    h2[m] = fmaxf(a, 0.f);
  }
}

__global__ void convTail(P p, int e0) {
  int e = e0 + threadIdx.x;
  if (e >= p.E) return;
  int s = p.src[e], d = p.dst[e];
  float ei0 = p.edge_inv[2*e], ei1 = p.edge_inv[2*e+1];
  float f0[16], f1[48];
  for (int i = 0; i < 16; i++) f0[i] = p.feat0[(size_t)s*16 + i];
  for (int i = 0; i < 48; i++) f1[i] = p.feat1[(size_t)s*48 + i];
  float h2[32], out0[16], o1[48];
  for (int c = 0; c < 16; c++) out0[c] = 0.f;
  for (int j = 0; j < 48; j++) o1[j] = 0.f;
  radial_g(p.w1[0], p.bb1[0], p.w2[0], p.bb2[0], ei0, ei1, h2);
  float bv = p.b00[e];
  for (int c = 0; c < 16; c++) {
    float v = 0.f;
    for (int k = 0; k < 16; k++) {
      float rw = 0.f;
      for (int m = 0; m < 32; m++) rw = fmaf(h2[m], p.w3[0][m*256 + c*16 + k], rw);
      v = fmaf(rw, f0[k], v);
    }
    out0[c] += v * bv;
  }
  radial_g(p.w1[1], p.bb1[1], p.w2[1], p.bb2[1], ei0, ei1, h2);
  float q0 = p.b01[e*3], q1 = p.b01[e*3+1], q2 = p.b01[e*3+2];
  for (int c = 0; c < 16; c++) {
    float v = 0.f;
    for (int k = 0; k < 16; k++) {
      float rw = 0.f;
      for (int m = 0; m < 32; m++) rw = fmaf(h2[m], p.w3[1][m*256 + c*16 + k], rw);
      v = fmaf(rw, f0[k], v);
    }
    o1[c*3] += v*q0; o1[c*3+1] += v*q1; o1[c*3+2] += v*q2;
  }
  radial_g(p.w1[2], p.bb1[2], p.w2[2], p.bb2[2], ei0, ei1, h2);
  float g0 = p.b10[e*3], g1 = p.b10[e*3+1], g2 = p.b10[e*3+2];
  for (int c = 0; c < 16; c++) {
    float v = 0.f;
    for (int k = 0; k < 16; k++) {
      float rw = 0.f;
      for (int m = 0; m < 32; m++) rw = fmaf(h2[m], p.w3[2][m*256 + c*16 + k], rw);
      v = fmaf(rw, f1[k*3]*g0 + f1[k*3+1]*g1 + f1[k*3+2]*g2, v);
    }
    out0[c] += v;
  }
  radial_g(p.w1[3], p.bb1[3], p.w2[3], p.bb2[3], ei0, ei1, h2);
  for (int c = 0; c < 16; c++) {
    for (int k = 0; k < 16; k++) {
      for (int f = 0; f < 3; f++) {
        float rw = 0.f;
        for (int m = 0; m < 32; m++) rw = fmaf(h2[m], p.w3[3][m*768 + c*48 + k*3 + f], rw);
        for (int o = 0; o < 3; o++) {
          float tt = f1[k*3]*p.b11[(size_t)e*27 + f*3 + o]
                   + f1[k*3+1]*p.b11[(size_t)e*27 + 9 + f*3 + o]
                   + f1[k*3+2]*p.b11[(size_t)e*27 + 18 + f*3 + o];
          o1[c*3+o] = fmaf(rw, tt, o1[c*3+o]);
        }
      }
    }
  }
  float* outp = p.out + (size_t)d * 64;
  for (int c = 0; c < 16; c++) {
    atomicAdd(outp + c*4,     out0[c]);
    atomicAdd(outp + c*4 + 1, o1[c*3]);
    atomicAdd(outp + c*4 + 2, o1[c*3+1]);
    atomicAdd(outp + c*4 + 3, o1[c*3+2]);
  }
}

}  // namespace

extern "C" void kernel_launch(void* const* d_in, const int* in_sizes, int n_in,
                              void* d_out, int out_size) {
  P p{};
  p.feat0    = (const float*)d_in[0];
  p.feat1    = (const float*)d_in[1];
  p.edge_inv = (const float*)d_in[2];
  p.src      = (const int*)d_in[3];
  p.dst      = (const int*)d_in[4];
  p.b00 = (const float*)d_in[5];
  p.b01 = (const float*)d_in[6];
  p.b10 = (const float*)d_in[7];
  p.b11 = (const float*)d_in[8];
  const int base[4] = {9, 14, 19, 24};   // 00, 01, 10, 11
  for (int pr = 0; pr < 4; pr++) {
    p.w1[pr]  = (const float*)d_in[base[pr]];
    p.bb1[pr] = (const float*)d_in[base[pr]+1];
    p.w2[pr]  = (const float*)d_in[base[pr]+2];
    p.bb2[pr] = (const float*)d_in[base[pr]+3];
    p.w3[pr]  = (const float*)d_in[base[pr]+4];
  }
  p.out = (float*)d_out;
  p.E = in_sizes[3];

  static bool attr_done = false;
  if (!attr_done) {
    cudaFuncSetAttribute(convFused, cudaFuncAttributeMaxDynamicSharedMemorySize,
                         S_TOT * 4);
    attr_done = true;
  }

  int nblk = (out_size + 255) / 256;
  if (nblk < 96) nblk = 96;
  prolog<<<nblk, 256>>>(p.w3[3], p.out, out_size);

  int nfull = p.E / 128;
  if (nfull > 0) convFused<<<nfull, 256, S_TOT * 4>>>(p);
  int tail = p.E - nfull * 128;
  if (tail > 0) convTail<<<1, tail>>>(p, nfull * 128);
}

// round 13
// speedup vs baseline: 1.1319x; 1.1319x over previous
#include <cuda_runtime.h>
#include <cstdint>

namespace {
using u64 = unsigned long long;

__device__ __forceinline__ u64 pk(float x) {
  u64 d; unsigned xi = __float_as_uint(x);
  asm("mov.b64 %0, {%1, %1};" : "=l"(d) : "r"(xi));
  return d;
}
__device__ __forceinline__ u64 ffma2(u64 a, u64 b, u64 c) {
  u64 d;
  asm("fma.rn.f32x2 %0, %1, %2, %3;" : "=l"(d) : "l"(a), "l"(b), "l"(c));
  return d;
}
__device__ __forceinline__ float2 unpk(u64 d) {
  unsigned lo, hi;
  asm("mov.b64 {%0, %1}, %2;" : "=r"(lo), "=r"(hi) : "l"(d));
  return make_float2(__uint_as_float(lo), __uint_as_float(hi));
}
__device__ __forceinline__ uint32_t cvt_tf32(float x) {
  uint32_t r;
  asm("cvt.rna.tf32.f32 %0, %1;" : "=r"(r) : "f"(x));
  return r;
}
__device__ __forceinline__ void mma_tf32(float d[4], const uint32_t a[4],
                                         uint32_t b0, uint32_t b1) {
  asm volatile(
      "mma.sync.aligned.m16n8k8.row.col.f32.tf32.tf32.f32 "
      "{%0,%1,%2,%3}, {%4,%5,%6,%7}, {%8,%9}, {%0,%1,%2,%3};"
      : "+f"(d[0]), "+f"(d[1]), "+f"(d[2]), "+f"(d[3])
      : "r"(a[0]), "r"(a[1]), "r"(a[2]), "r"(a[3]), "r"(b0), "r"(b1));
}

struct P {
  const float *feat0, *feat1, *edge_inv;
  const int *src, *dst;
  const float *b00, *b01, *b10, *b11;
  const float *w1[4], *bb1[4], *w2[4], *bb2[4], *w3[4];  // 00,01,10,11
  float* out;
  int E;
};

// All 6 W3 chunks in mma fragment-major layout, tf32-pre-rounded.
// chunk: 0=p00, 1=p01, 2=p10, 3..5=p11 f=0..2.  Within a chunk (8192 floats):
//   idx = ((kt2*32 + nt)*32 + lane)*4 + ktb*2 + sel
//   kdim = (kt2*2+ktb)*8 + sel*4 + (lane&3);  n = nt*8 + (lane>>2)
__device__ float g_W3F[49152];

__global__ void prolog(P p, int nout) {
  int i = blockIdx.x * 256 + threadIdx.x;
  if (i < nout) p.out[i] = 0.f;
  if (i < 49152) {
    int chunk = i >> 13;
    int il = i & 8191;
    int sel = il & 1;
    int ktb = (il >> 1) & 1;
    int lane = (il >> 2) & 31;
    int nt = (il >> 7) & 31;
    int kt2 = (il >> 12) & 1;
    int q = lane & 3, r = lane >> 2;
    int kdim = (kt2*2 + ktb)*8 + sel*4 + q;   // GEMM k index (0..31)
    int n = nt*8 + r;                          // GEMM n index (0..255)
    int c = n >> 4, k = n & 15;
    float v;
    if (chunk < 3) {
      const float* w3 = (chunk == 0) ? p.w3[0] : ((chunk == 1) ? p.w3[1] : p.w3[2]);
      v = w3[kdim*256 + c*16 + k];
    } else {
      v = p.w3[3][kdim*768 + c*48 + k*3 + (chunk - 3)];
    }
    g_W3F[i] = __uint_as_float(cvt_tf32(v));
  }
}

// smem float offsets
constexpr int S_F0  = 0;        // [128][16]  f0; reused as t1 before pair10
constexpr int S_F1  = 2048;     // [128][48]
constexpr int S_EB  = 8192;     // [128][10]
constexpr int S_B11 = 9472;     // [128][27]
constexpr int S_H2  = 12928;    // [128][36] padded rows (tf32 bits)
constexpr int S_W3  = 17536;    // [8192]  fragment-major B tile
constexpr int S_MLPA= 25856;    // 1152
constexpr int S_MLPB= 27008;    // 1152
constexpr int S_TOT = 28160;    // 112640 B (x2 CTA = 225 KB)

__device__ __forceinline__ void radial_half(const float* __restrict__ mlp,
                                            float ei0, float ei1, int mhalf,
                                            float h2[16]) {
  const float* w1 = mlp; const float* b1 = mlp + 64;
  const float* w2 = mlp + 96; const float* b2 = mlp + 1120;
  float h1[32];
#pragma unroll
  for (int j = 0; j < 32; j++)
    h1[j] = fmaxf(fmaf(ei0, w1[j], fmaf(ei1, w1[32 + j], b1[j])), 0.f);
  u64 acc[8];
  const u64* b2p = reinterpret_cast<const u64*>(b2 + mhalf);
#pragma unroll
  for (int j = 0; j < 8; j++) acc[j] = b2p[j];
#pragma unroll
  for (int n = 0; n < 32; n++) {
    u64 h = pk(h1[n]);
    const u64* wrow = reinterpret_cast<const u64*>(w2 + n*32 + mhalf);
#pragma unroll
    for (int j = 0; j < 8; j++) acc[j] = ffma2(h, wrow[j], acc[j]);
  }
#pragma unroll
  for (int j = 0; j < 8; j++) {
    float2 q = unpk(acc[j]);
    h2[2*j]   = fmaxf(q.x, 0.f);
    h2[2*j+1] = fmaxf(q.y, 0.f);
  }
}

// Guard-free main kernel: every block covers 128 valid edges.
__global__ void __launch_bounds__(256, 2) convFused(P p) {
  extern __shared__ float sm[];
  int t = threadIdx.x;
  int eb = blockIdx.x * 128;
  int w = t >> 5, lane = t & 31;
  int r = lane >> 2, q = lane & 3;
  int el0 = w*16 + r, el1 = el0 + 8;
  int el2 = t >> 1, mhalf = (t & 1) * 16;

  // ---------- stage per-edge data ----------
  if (t < 128) {
    int e = eb + t;
    float* EB = sm + S_EB + t*10;
    EB[0] = p.edge_inv[2*e];
    EB[1] = p.edge_inv[2*e+1];
    EB[2] = p.b00[e];
    EB[3] = p.b01[3*e]; EB[4] = p.b01[3*e+1]; EB[5] = p.b01[3*e+2];
    EB[6] = p.b10[3*e]; EB[7] = p.b10[3*e+1]; EB[8] = p.b10[3*e+2];
    reinterpret_cast<int*>(EB)[9] = p.dst[e];
  }
  {
    int half = t & 1;
    int e = eb + el2;
    int s = p.src[e];
    const float4* f0g = reinterpret_cast<const float4*>(p.feat0 + (size_t)s*16);
    float4* f0s = reinterpret_cast<float4*>(sm + S_F0 + el2*16);
    f0s[half*2+0] = f0g[half*2+0];
    f0s[half*2+1] = f0g[half*2+1];
    const float4* f1g = reinterpret_cast<const float4*>(p.feat1 + (size_t)s*48);
    float4* f1s = reinterpret_cast<float4*>(sm + S_F1 + el2*48);
#pragma unroll
    for (int qq = 0; qq < 6; qq++) f1s[half*6+qq] = f1g[half*6+qq];
    const float* bg = p.b11 + (size_t)e*27;
    float* bs = sm + S_B11 + el2*27;
    for (int qq = half; qq < 27; qq += 2) bs[qq] = bg[qq];
  }

  auto stage_mlp = [&](int pr, int off) {
    float* d = sm + off;
    if (t < 64) d[t] = p.w1[pr][t];
    else if (t < 96) d[64 + (t-64)] = p.bb1[pr][t-64];
    else if (t < 128) d[1120 + (t-96)] = p.bb2[pr][t-96];
    for (int i = t; i < 1024; i += 256) d[96 + i] = p.w2[pr][i];
  };
  auto do_radial = [&](int off, bool fold) {
    const float* EB = sm + S_EB + el2*10;
    float h2[16];
    radial_half(sm + off, EB[0], EB[1], mhalf, h2);
    float sc = fold ? EB[2] : 1.f;
#pragma unroll
    for (int j = 0; j < 16; j++)
      sm[S_H2 + el2*36 + mhalf + j] = __uint_as_float(cvt_tf32(h2[j] * sc));
  };
  auto w3load = [&](const float* __restrict__ g, float4 rr[8]) {
    const float4* s4 = reinterpret_cast<const float4*>(g);
#pragma unroll
    for (int qq = 0; qq < 8; qq++) rr[qq] = s4[t + 256*qq];
  };
  auto w3store = [&](const float4 rr[8]) {
    float4* d = reinterpret_cast<float4*>(sm + S_W3);
#pragma unroll
    for (int qq = 0; qq < 8; qq++) d[t + 256*qq] = rr[qq];
  };
  auto loadA = [&](uint32_t A[4][4]) {
#pragma unroll
    for (int kt = 0; kt < 4; kt++) {
      A[kt][0] = __float_as_uint(sm[S_H2 + el0*36 + kt*8 + q]);
      A[kt][1] = __float_as_uint(sm[S_H2 + el1*36 + kt*8 + q]);
      A[kt][2] = __float_as_uint(sm[S_H2 + el0*36 + kt*8 + q + 4]);
      A[kt][3] = __float_as_uint(sm[S_H2 + el1*36 + kt*8 + q + 4]);
    }
  };
  auto mma_slice = [&](const uint32_t A[4][4], int ns, float D[8][4]) {
#pragma unroll
    for (int i = 0; i < 8; i++)
#pragma unroll
      for (int j = 0; j < 4; j++) D[i][j] = 0.f;
    const float4* F = reinterpret_cast<const float4*>(sm + S_W3);
#pragma unroll
    for (int nt8 = 0; nt8 < 8; nt8++) {
      int nt = ns*8 + nt8;
      float4 v1 = F[nt*32 + lane];           // kt 0,1
      float4 v2 = F[1024 + nt*32 + lane];    // kt 2,3
      mma_tf32(D[nt8], A[0], __float_as_uint(v1.x), __float_as_uint(v1.y));
      mma_tf32(D[nt8], A[1], __float_as_uint(v1.z), __float_as_uint(v1.w));
      mma_tf32(D[nt8], A[2], __float_as_uint(v2.x), __float_as_uint(v2.y));
      mma_tf32(D[nt8], A[3], __float_as_uint(v2.z), __float_as_uint(v2.w));
    }
  };

  // vec-dot epilogue (pairs 00/01/10): vec in S_F0; mode 0 -> deg0, 1 -> deg1*b01
  auto chunk_vec = [&](int mode) {
    uint32_t A[4][4];
    loadA(A);
    float fa0 = sm[S_F0 + el0*16 + 2*q],     fa1 = sm[S_F0 + el0*16 + 2*q + 1];
    float fa2 = sm[S_F0 + el0*16 + 2*q + 8], fa3 = sm[S_F0 + el0*16 + 2*q + 9];
    float fb0 = sm[S_F0 + el1*16 + 2*q],     fb1 = sm[S_F0 + el1*16 + 2*q + 1];
    float fb2 = sm[S_F0 + el1*16 + 2*q + 8], fb3 = sm[S_F0 + el1*16 + 2*q + 9];
#pragma unroll 1
    for (int ns = 0; ns < 4; ns++) {
      float D[8][4];
      mma_slice(A, ns, D);
#pragma unroll
      for (int cc = 0; cc < 4; cc++) {
        int c = ns*4 + cc;
        float v0 = D[cc*2][0]*fa0 + D[cc*2][1]*fa1 + D[cc*2+1][0]*fa2 + D[cc*2+1][1]*fa3;
        float v1 = D[cc*2][2]*fb0 + D[cc*2][3]*fb1 + D[cc*2+1][2]*fb2 + D[cc*2+1][3]*fb3;
        v0 += __shfl_xor_sync(0xffffffffu, v0, 1);
        v0 += __shfl_xor_sync(0xffffffffu, v0, 2);
        v1 += __shfl_xor_sync(0xffffffffu, v1, 1);
        v1 += __shfl_xor_sync(0xffffffffu, v1, 2);
        if (q == 0) {
          const float* E0 = sm + S_EB + el0*10;
          const float* E1 = sm + S_EB + el1*10;
          int d0 = reinterpret_cast<const int*>(E0)[9];
          int d1 = reinterpret_cast<const int*>(E1)[9];
          if (mode == 0) {
            atomicAdd(p.out + (size_t)d0*64 + c*4, v0);
            atomicAdd(p.out + (size_t)d1*64 + c*4, v1);
          } else {
            float* o0 = p.out + (size_t)d0*64 + c*4;
            float* o1 = p.out + (size_t)d1*64 + c*4;
            atomicAdd(o0 + 1, v0*E0[3]); atomicAdd(o0 + 2, v0*E0[4]); atomicAdd(o0 + 3, v0*E0[5]);
            atomicAdd(o1 + 1, v1*E1[3]); atomicAdd(o1 + 2, v1*E1[4]); atomicAdd(o1 + 3, v1*E1[5]);
          }
        }
      }
    }
  };

  float4 wreg[8];

  stage_mlp(0, S_MLPA);
  __syncthreads();

  // ---- chunk 0: pair00 (b00 folded) -> deg0 ----
  w3load(g_W3F, wreg);
  do_radial(S_MLPA, true);
  w3store(wreg);
  __syncthreads();
  chunk_vec(0);
  stage_mlp(1, S_MLPB);
  w3load(g_W3F + 8192, wreg);
  __syncthreads();

  // ---- chunk 1: pair01 -> deg1 (x b01) ----
  do_radial(S_MLPB, false);
  w3store(wreg);
  __syncthreads();
  chunk_vec(1);
  stage_mlp(2, S_MLPA);
  w3load(g_W3F + 16384, wreg);
  __syncthreads();

  // ---- chunk 2: pair10 -> deg0; t1 precomputed into S_F0 ----
  do_radial(S_MLPA, false);
  {
    int half = t & 1, kh = half*8;
    const float* EB = sm + S_EB + el2*10;
    float g0 = EB[6], g1 = EB[7], g2 = EB[8];
    const float* f1 = sm + S_F1 + el2*48 + kh*3;
    float* t1 = sm + S_F0 + el2*16 + kh;
#pragma unroll
    for (int j = 0; j < 8; j++)
      t1[j] = f1[j*3]*g0 + f1[j*3+1]*g1 + f1[j*3+2]*g2;
  }
  w3store(wreg);
  __syncthreads();
  chunk_vec(0);
  stage_mlp(3, S_MLPB);
  w3load(g_W3F + 24576, wreg);
  __syncthreads();

  // ---- chunks 3..5: pair11 (f = 0,1,2) -> deg1 ----
  do_radial(S_MLPB, false);
  w3store(wreg);
  __syncthreads();
  {
    uint32_t A[4][4];
    loadA(A);
    float ga[4][3], gb[4][3];
    int kfs[4] = {2*q, 2*q + 1, 2*q + 8, 2*q + 9};
#pragma unroll
    for (int s2 = 0; s2 < 4; s2++)
#pragma unroll
      for (int i = 0; i < 3; i++) {
        ga[s2][i] = sm[S_F1 + el0*48 + kfs[s2]*3 + i];
        gb[s2][i] = sm[S_F1 + el1*48 + kfs[s2]*3 + i];
      }
#pragma unroll 1
    for (int f = 0; f < 3; f++) {
#pragma unroll 1
      for (int ns = 0; ns < 4; ns++) {
        float D[8][4];
        mma_slice(A, ns, D);
#pragma unroll
        for (int cc = 0; cc < 4; cc++) {
          int c = ns*4 + cc;
          float s0a = D[cc*2][0]*ga[0][0] + D[cc*2][1]*ga[1][0] + D[cc*2+1][0]*ga[2][0] + D[cc*2+1][1]*ga[3][0];
          float s1a = D[cc*2][0]*ga[0][1] + D[cc*2][1]*ga[1][1] + D[cc*2+1][0]*ga[2][1] + D[cc*2+1][1]*ga[3][1];
          float s2a = D[cc*2][0]*ga[0][2] + D[cc*2][1]*ga[1][2] + D[cc*2+1][0]*ga[2][2] + D[cc*2+1][1]*ga[3][2];
          float s0b = D[cc*2][2]*gb[0][0] + D[cc*2][3]*gb[1][0] + D[cc*2+1][2]*gb[2][0] + D[cc*2+1][3]*gb[3][0];
          float s1b = D[cc*2][2]*gb[0][1] + D[cc*2][3]*gb[1][1] + D[cc*2+1][2]*gb[2][1] + D[cc*2+1][3]*gb[3][1];
          float s2b = D[cc*2][2]*gb[0][2] + D[cc*2][3]*gb[1][2] + D[cc*2+1][2]*gb[2][2] + D[cc*2+1][3]*gb[3][2];
          s0a += __shfl_xor_sync(0xffffffffu, s0a, 1); s0a += __shfl_xor_sync(0xffffffffu, s0a, 2);
          s1a += __shfl_xor_sync(0xffffffffu, s1a, 1); s1a += __shfl_xor_sync(0xffffffffu, s1a, 2);
          s2a += __shfl_xor_sync(0xffffffffu, s2a, 1); s2a += __shfl_xor_sync(0xffffffffu, s2a, 2);
          s0b += __shfl_xor_sync(0xffffffffu, s0b, 1); s0b += __shfl_xor_sync(0xffffffffu, s0b, 2);
          s1b += __shfl_xor_sync(0xffffffffu, s1b, 1); s1b += __shfl_xor_sync(0xffffffffu, s1b, 2);
          s2b += __shfl_xor_sync(0xffffffffu, s2b, 1); s2b += __shfl_xor_sync(0xffffffffu, s2b, 2);
          if (q == 0) {
            const float* Ba = sm + S_B11 + el0*27 + f*3;   // B[i*9 + f*3 + o]
            const float* Bb = sm + S_B11 + el1*27 + f*3;
            int d0 = reinterpret_cast<const int*>(sm + S_EB + el0*10)[9];
            int d1 = reinterpret_cast<const int*>(sm + S_EB + el1*10)[9];
            float* oa = p.out + (size_t)d0*64 + c*4;
            float* ob = p.out + (size_t)d1*64 + c*4;
            atomicAdd(oa + 1, s0a*Ba[0] + s1a*Ba[9]  + s2a*Ba[18]);
            atomicAdd(oa + 2, s0a*Ba[1] + s1a*Ba[10] + s2a*Ba[19]);
            atomicAdd(oa + 3, s0a*Ba[2] + s1a*Ba[11] + s2a*Ba[20]);
            atomicAdd(ob + 1, s0b*Bb[0] + s1b*Bb[9]  + s2b*Bb[18]);
            atomicAdd(ob + 2, s0b*Bb[1] + s1b*Bb[10] + s2b*Bb[19]);
            atomicAdd(ob + 3, s0b*Bb[2] + s1b*Bb[11] + s2b*Bb[20]);
          }
        }
      }
      if (f < 2) {
        w3load(g_W3F + (4 + f)*8192, wreg);
        __syncthreads();
        w3store(wreg);
        __syncthreads();
      }
    }
  }
}

// ---------- scalar tail (E % 128 edges; weights from gmem) ----------
__device__ void radial_g(const float* w1, const float* b1, const float* w2,
                         const float* b2, float ei0, float ei1, float h2[32]) {
  float h1[32];
  for (int m = 0; m < 32; m++)
    h1[m] = fmaxf(fmaf(ei0, w1[m], fmaf(ei1, w1[32+m], b1[m])), 0.f);
  for (int m = 0; m < 32; m++) {
    float a = b2[m];
    for (int n = 0; n < 32; n++) a = fmaf(h1[n], w2[n*32 + m], a);
    h2[m] = fmaxf(a, 0.f);
  }
}

__global__ void convTail(P p, int e0) {
  int e = e0 + threadIdx.x;
  if (e >= p.E) return;
  int s = p.src[e], d = p.dst[e];
  float ei0 = p.edge_inv[2*e], ei1 = p.edge_inv[2*e+1];
  float f0[16], f1[48];
  for (int i = 0; i < 16; i++) f0[i] = p.feat0[(size_t)s*16 + i];
  for (int i = 0; i < 48; i++) f1[i] = p.feat1[(size_t)s*48 + i];
  float h2[32], out0[16], o1[48];
  for (int c = 0; c < 16; c++) out0[c] = 0.f;
  for (int j = 0; j < 48; j++) o1[j] = 0.f;
  radial_g(p.w1[0], p.bb1[0], p.w2[0], p.bb2[0], ei0, ei1, h2);
  float bv = p.b00[e];
  for (int c = 0; c < 16; c++) {
    float v = 0.f;
    for (int k = 0; k < 16; k++) {
      float rw = 0.f;
      for (int m = 0; m < 32; m++) rw = fmaf(h2[m], p.w3[0][m*256 + c*16 + k], rw);
      v = fmaf(rw, f0[k], v);
    }
    out0[c] += v * bv;
  }
  radial_g(p.w1[1], p.bb1[1], p.w2[1], p.bb2[1], ei0, ei1, h2);
  float q0 = p.b01[e*3], q1 = p.b01[e*3+1], q2 = p.b01[e*3+2];
  for (int c = 0; c < 16; c++) {
    float v = 0.f;
    for (int k = 0; k < 16; k++) {
      float rw = 0.f;
      for (int m = 0; m < 32; m++) rw = fmaf(h2[m], p.w3[1][m*256 + c*16 + k], rw);
      v = fmaf(rw, f0[k], v);
    }
    o1[c*3] += v*q0; o1[c*3+1] += v*q1; o1[c*3+2] += v*q2;
  }
  radial_g(p.w1[2], p.bb1[2], p.w2[2], p.bb2[2], ei0, ei1, h2);
  float g0 = p.b10[e*3], g1 = p.b10[e*3+1], g2 = p.b10[e*3+2];
  for (int c = 0; c < 16; c++) {
    float v = 0.f;
    for (int k = 0; k < 16; k++) {
      float rw = 0.f;
      for (int m = 0; m < 32; m++) rw = fmaf(h2[m], p.w3[2][m*256 + c*16 + k], rw);
      v = fmaf(rw, f1[k*3]*g0 + f1[k*3+1]*g1 + f1[k*3+2]*g2, v);
    }
    out0[c] += v;
  }
  radial_g(p.w1[3], p.bb1[3], p.w2[3], p.bb2[3], ei0, ei1, h2);
  for (int c = 0; c < 16; c++) {
    for (int k = 0; k < 16; k++) {
      for (int f = 0; f < 3; f++) {
        float rw = 0.f;
        for (int m = 0; m < 32; m++) rw = fmaf(h2[m], p.w3[3][m*768 + c*48 + k*3 + f], rw);
        for (int o = 0; o < 3; o++) {
          float tt = f1[k*3]*p.b11[(size_t)e*27 + f*3 + o]
                   + f1[k*3+1]*p.b11[(size_t)e*27 + 9 + f*3 + o]
                   + f1[k*3+2]*p.b11[(size_t)e*27 + 18 + f*3 + o];
          o1[c*3+o] = fmaf(rw, tt, o1[c*3+o]);
        }
      }
    }
  }
  float* outp = p.out + (size_t)d * 64;
  for (int c = 0; c < 16; c++) {
    atomicAdd(outp + c*4,     out0[c]);
    atomicAdd(outp + c*4 + 1, o1[c*3]);
    atomicAdd(outp + c*4 + 2, o1[c*3+1]);
    atomicAdd(outp + c*4 + 3, o1[c*3+2]);
  }
}

}  // namespace

extern "C" void kernel_launch(void* const* d_in, const int* in_sizes, int n_in,
                              void* d_out, int out_size) {
  P p{};
  p.feat0    = (const float*)d_in[0];
  p.feat1    = (const float*)d_in[1];
  p.edge_inv = (const float*)d_in[2];
  p.src      = (const int*)d_in[3];
  p.dst      = (const int*)d_in[4];
  p.b00 = (const float*)d_in[5];
  p.b01 = (const float*)d_in[6];
  p.b10 = (const float*)d_in[7];
  p.b11 = (const float*)d_in[8];
  const int base[4] = {9, 14, 19, 24};   // 00, 01, 10, 11
  for (int pr = 0; pr < 4; pr++) {
    p.w1[pr]  = (const float*)d_in[base[pr]];
    p.bb1[pr] = (const float*)d_in[base[pr]+1];
    p.w2[pr]  = (const float*)d_in[base[pr]+2];
    p.bb2[pr] = (const float*)d_in[base[pr]+3];
    p.w3[pr]  = (const float*)d_in[base[pr]+4];
  }
  p.out = (float*)d_out;
  p.E = in_sizes[3];

  static bool attr_done = false;
  if (!attr_done) {
    cudaFuncSetAttribute(convFused, cudaFuncAttributeMaxDynamicSharedMemorySize,
                         S_TOT * 4);
    attr_done = true;
  }

  int nblk = (out_size + 255) / 256;
  if (nblk < 192) nblk = 192;
  prolog<<<nblk, 256>>>(p, out_size);

  int nfull = p.E / 128;
  if (nfull > 0) convFused<<<nfull, 256, S_TOT * 4>>>(p);
  int tail = p.E - nfull * 128;
  if (tail > 0) convTail<<<1, tail>>>(p, nfull * 128);
}

// round 14
// speedup vs baseline: 1.2002x; 1.0603x over previous
#include <cuda_runtime.h>
#include <cstdint>

namespace {
using u64 = unsigned long long;

__device__ __forceinline__ u64 pk(float x) {
  u64 d; unsigned xi = __float_as_uint(x);
  asm("mov.b64 %0, {%1, %1};" : "=l"(d) : "r"(xi));
  return d;
}
__device__ __forceinline__ u64 ffma2(u64 a, u64 b, u64 c) {
  u64 d;
  asm("fma.rn.f32x2 %0, %1, %2, %3;" : "=l"(d) : "l"(a), "l"(b), "l"(c));
  return d;
}
__device__ __forceinline__ float2 unpk(u64 d) {
  unsigned lo, hi;
  asm("mov.b64 {%0, %1}, %2;" : "=r"(lo), "=r"(hi) : "l"(d));
  return make_float2(__uint_as_float(lo), __uint_as_float(hi));
}
__device__ __forceinline__ uint32_t cvt_tf32(float x) {
  uint32_t r;
  asm("cvt.rna.tf32.f32 %0, %1;" : "=r"(r) : "f"(x));
  return r;
}
__device__ __forceinline__ void mma_tf32(float d[4], const uint32_t a[4],
                                         uint32_t b0, uint32_t b1) {
  asm volatile(
      "mma.sync.aligned.m16n8k8.row.col.f32.tf32.tf32.f32 "
      "{%0,%1,%2,%3}, {%4,%5,%6,%7}, {%8,%9}, {%0,%1,%2,%3};"
      : "+f"(d[0]), "+f"(d[1]), "+f"(d[2]), "+f"(d[3])
      : "r"(a[0]), "r"(a[1]), "r"(a[2]), "r"(a[3]), "r"(b0), "r"(b1));
}

struct P {
  const float *feat0, *feat1, *edge_inv;
  const int *src, *dst;
  const float *b00, *b01, *b10, *b11;
  const float *w1[4], *bb1[4], *w2[4], *bb2[4], *w3[4];  // 00,01,10,11
  float* out;
  int E;
};

// All 6 W3 chunks in mma fragment-major layout, tf32-pre-rounded.
// idx = ((kt2*32 + nt)*32 + lane)*4 + ktb*2 + sel
// kdim = (kt2*2+ktb)*8 + sel*4 + (lane&3);  n = nt*8 + (lane>>2)
__device__ float g_W3F[49152];

__global__ void prolog(P p, int nout) {
  int i = blockIdx.x * 256 + threadIdx.x;
  if (i < nout) p.out[i] = 0.f;
  if (i < 49152) {
    int chunk = i >> 13;
    int il = i & 8191;
    int sel = il & 1;
    int ktb = (il >> 1) & 1;
    int lane = (il >> 2) & 31;
    int nt = (il >> 7) & 31;
    int kt2 = (il >> 12) & 1;
    int q = lane & 3, r = lane >> 2;
    int kdim = (kt2*2 + ktb)*8 + sel*4 + q;
    int n = nt*8 + r;
    int c = n >> 4, k = n & 15;
    float v;
    if (chunk < 3) {
      const float* w3 = (chunk == 0) ? p.w3[0] : ((chunk == 1) ? p.w3[1] : p.w3[2]);
      v = w3[kdim*256 + c*16 + k];
    } else {
      v = p.w3[3][kdim*768 + c*48 + k*3 + (chunk - 3)];
    }
    g_W3F[i] = __uint_as_float(cvt_tf32(v));
  }
}

// smem float offsets
constexpr int S_F0  = 0;        // [128][16]  f0; reused as t1 before pair10
constexpr int S_F1  = 2048;     // [128][48]
constexpr int S_EB  = 8192;     // [128][10]
constexpr int S_B11 = 9472;     // [128][27]
constexpr int S_H2  = 12928;    // [128][36] padded rows (tf32 bits)
constexpr int S_W3  = 17536;    // [8192]  fragment-major B tile
constexpr int S_MLPA= 25856;    // 1152
constexpr int S_MLPB= 27008;    // 1152
constexpr int S_TOT = 28160;    // 112640 B (x2 CTA = 225 KB)

__device__ __forceinline__ void radial_half(const float* __restrict__ mlp,
                                            float ei0, float ei1, int mhalf,
                                            float h2[16]) {
  const float* w1 = mlp; const float* b1 = mlp + 64;
  const float* w2 = mlp + 96; const float* b2 = mlp + 1120;
  float h1[32];
#pragma unroll
  for (int j = 0; j < 32; j++)
    h1[j] = fmaxf(fmaf(ei0, w1[j], fmaf(ei1, w1[32 + j], b1[j])), 0.f);
  u64 acc[8];
  const ulonglong2* b2p = reinterpret_cast<const ulonglong2*>(b2 + mhalf);
#pragma unroll
  for (int j = 0; j < 4; j++) {
    ulonglong2 b = b2p[j];
    acc[j*2] = b.x; acc[j*2+1] = b.y;
  }
#pragma unroll
  for (int n = 0; n < 32; n++) {
    u64 h = pk(h1[n]);
    const ulonglong2* wrow = reinterpret_cast<const ulonglong2*>(w2 + n*32 + mhalf);
    ulonglong2 p0 = wrow[0], p1 = wrow[1], p2 = wrow[2], p3 = wrow[3];
    acc[0] = ffma2(h, p0.x, acc[0]); acc[1] = ffma2(h, p0.y, acc[1]);
    acc[2] = ffma2(h, p1.x, acc[2]); acc[3] = ffma2(h, p1.y, acc[3]);
    acc[4] = ffma2(h, p2.x, acc[4]); acc[5] = ffma2(h, p2.y, acc[5]);
    acc[6] = ffma2(h, p3.x, acc[6]); acc[7] = ffma2(h, p3.y, acc[7]);
  }
#pragma unroll
  for (int j = 0; j < 8; j++) {
    float2 q = unpk(acc[j]);
    h2[2*j]   = fmaxf(q.x, 0.f);
    h2[2*j+1] = fmaxf(q.y, 0.f);
  }
}

// Guard-free main kernel: every block covers 128 valid edges.
// Warp tiling: warp w -> edge quarter we = w>>1 (32 edges), n-half wn = w&1 (128 cols).
__global__ void __launch_bounds__(256, 2) convFused(P p) {
  extern __shared__ float sm[];
  int t = threadIdx.x;
  int eb = blockIdx.x * 128;
  int w = t >> 5, lane = t & 31;
  int r = lane >> 2, q = lane & 3;
  int we = w >> 1, wn = w & 1;
  int ebase = we * 32;
  int el[4] = {ebase + r, ebase + r + 8, ebase + r + 16, ebase + r + 24};
  int el2 = t >> 1, mhalf = (t & 1) * 16;

  // ---------- stage per-edge data ----------
  if (t < 128) {
    int e = eb + t;
    float* EB = sm + S_EB + t*10;
    EB[0] = p.edge_inv[2*e];
    EB[1] = p.edge_inv[2*e+1];
    EB[2] = p.b00[e];
    EB[3] = p.b01[3*e]; EB[4] = p.b01[3*e+1]; EB[5] = p.b01[3*e+2];
    EB[6] = p.b10[3*e]; EB[7] = p.b10[3*e+1]; EB[8] = p.b10[3*e+2];
    reinterpret_cast<int*>(EB)[9] = p.dst[e];
  }
  {
    int half = t & 1;
    int e = eb + el2;
    int s = p.src[e];
    const float4* f0g = reinterpret_cast<const float4*>(p.feat0 + (size_t)s*16);
    float4* f0s = reinterpret_cast<float4*>(sm + S_F0 + el2*16);
    f0s[half*2+0] = f0g[half*2+0];
    f0s[half*2+1] = f0g[half*2+1];
    const float4* f1g = reinterpret_cast<const float4*>(p.feat1 + (size_t)s*48);
    float4* f1s = reinterpret_cast<float4*>(sm + S_F1 + el2*48);
#pragma unroll
    for (int qq = 0; qq < 6; qq++) f1s[half*6+qq] = f1g[half*6+qq];
    const float* bg = p.b11 + (size_t)e*27;
    float* bs = sm + S_B11 + el2*27;
    for (int qq = half; qq < 27; qq += 2) bs[qq] = bg[qq];
  }

  auto stage_mlp = [&](int pr, int off) {
    float* d = sm + off;
    if (t < 64) d[t] = p.w1[pr][t];
    else if (t < 96) d[64 + (t-64)] = p.bb1[pr][t-64];
    else if (t < 128) d[1120 + (t-96)] = p.bb2[pr][t-96];
    for (int i = t; i < 1024; i += 256) d[96 + i] = p.w2[pr][i];
  };
  auto do_radial = [&](int off, bool fold) {
    const float* EB = sm + S_EB + el2*10;
    float h2[16];
    radial_half(sm + off, EB[0], EB[1], mhalf, h2);
    float sc = fold ? EB[2] : 1.f;
#pragma unroll
    for (int j = 0; j < 16; j++)
      sm[S_H2 + el2*36 + mhalf + j] = __uint_as_float(cvt_tf32(h2[j] * sc));
  };
  auto w3load = [&](const float* __restrict__ g, float4 rr[8]) {
    const float4* s4 = reinterpret_cast<const float4*>(g);
#pragma unroll
    for (int qq = 0; qq < 8; qq++) rr[qq] = s4[t + 256*qq];
  };
  auto w3store = [&](const float4 rr[8]) {
    float4* d = reinterpret_cast<float4*>(sm + S_W3);
#pragma unroll
    for (int qq = 0; qq < 8; qq++) d[t + 256*qq] = rr[qq];
  };
  // A fragments for both m16 tiles (edges ebase..+15, ebase+16..+31)
  auto loadA2 = [&](uint32_t A0[4][4], uint32_t A1[4][4]) {
#pragma unroll
    for (int kt = 0; kt < 4; kt++) {
      A0[kt][0] = __float_as_uint(sm[S_H2 + el[0]*36 + kt*8 + q]);
      A0[kt][1] = __float_as_uint(sm[S_H2 + el[1]*36 + kt*8 + q]);
      A0[kt][2] = __float_as_uint(sm[S_H2 + el[0]*36 + kt*8 + q + 4]);
      A0[kt][3] = __float_as_uint(sm[S_H2 + el[1]*36 + kt*8 + q + 4]);
      A1[kt][0] = __float_as_uint(sm[S_H2 + el[2]*36 + kt*8 + q]);
      A1[kt][1] = __float_as_uint(sm[S_H2 + el[3]*36 + kt*8 + q]);
      A1[kt][2] = __float_as_uint(sm[S_H2 + el[2]*36 + kt*8 + q + 4]);
      A1[kt][3] = __float_as_uint(sm[S_H2 + el[3]*36 + kt*8 + q + 4]);
    }
  };
  // One c-column (2 nt) for both m tiles: D0 = tile0 {nt0,nt1}, D1 = tile1.
  auto mma_cl = [&](const uint32_t A0[4][4], const uint32_t A1[4][4], int nt0,
                    float D0[2][4], float D1[2][4]) {
#pragma unroll
    for (int i = 0; i < 2; i++)
#pragma unroll
      for (int j = 0; j < 4; j++) { D0[i][j] = 0.f; D1[i][j] = 0.f; }
    const float4* F = reinterpret_cast<const float4*>(sm + S_W3);
    float4 va1 = F[nt0*32 + lane];
    float4 va2 = F[1024 + nt0*32 + lane];
    float4 vb1 = F[(nt0+1)*32 + lane];
    float4 vb2 = F[1024 + (nt0+1)*32 + lane];
    uint32_t a10 = __float_as_uint(va1.x), a11 = __float_as_uint(va1.y);
    uint32_t a12 = __float_as_uint(va1.z), a13 = __float_as_uint(va1.w);
    uint32_t a20 = __float_as_uint(va2.x), a21 = __float_as_uint(va2.y);
    uint32_t a22 = __float_as_uint(va2.z), a23 = __float_as_uint(va2.w);
    uint32_t b10 = __float_as_uint(vb1.x), b11 = __float_as_uint(vb1.y);
    uint32_t b12 = __float_as_uint(vb1.z), b13 = __float_as_uint(vb1.w);
    uint32_t b20 = __float_as_uint(vb2.x), b21 = __float_as_uint(vb2.y);
    uint32_t b22 = __float_as_uint(vb2.z), b23 = __float_as_uint(vb2.w);
    mma_tf32(D0[0], A0[0], a10, a11); mma_tf32(D0[0], A0[1], a12, a13);
    mma_tf32(D0[0], A0[2], a20, a21); mma_tf32(D0[0], A0[3], a22, a23);
    mma_tf32(D0[1], A0[0], b10, b11); mma_tf32(D0[1], A0[1], b12, b13);
    mma_tf32(D0[1], A0[2], b20, b21); mma_tf32(D0[1], A0[3], b22, b23);
    mma_tf32(D1[0], A1[0], a10, a11); mma_tf32(D1[0], A1[1], a12, a13);
    mma_tf32(D1[0], A1[2], a20, a21); mma_tf32(D1[0], A1[3], a22, a23);
    mma_tf32(D1[1], A1[0], b10, b11); mma_tf32(D1[1], A1[1], b12, b13);
    mma_tf32(D1[1], A1[2], b20, b21); mma_tf32(D1[1], A1[3], b22, b23);
  };

  // vec-dot epilogue (pairs 00/01/10): vec in S_F0; mode 0 -> deg0, 1 -> deg1*b01
  auto chunk_vec = [&](int mode) {
    uint32_t A0[4][4], A1[4][4];
    loadA2(A0, A1);
    float fA[4][4];
#pragma unroll
    for (int i = 0; i < 4; i++) {
      fA[i][0] = sm[S_F0 + el[i]*16 + 2*q];
      fA[i][1] = sm[S_F0 + el[i]*16 + 2*q + 1];
      fA[i][2] = sm[S_F0 + el[i]*16 + 2*q + 8];
      fA[i][3] = sm[S_F0 + el[i]*16 + 2*q + 9];
    }
#pragma unroll 1
    for (int cl = 0; cl < 8; cl++) {
      int nt0 = wn*16 + cl*2;
      float D0[2][4], D1[2][4];
      mma_cl(A0, A1, nt0, D0, D1);
      int c = wn*8 + cl;
      float v[4];
      v[0] = D0[0][0]*fA[0][0] + D0[0][1]*fA[0][1] + D0[1][0]*fA[0][2] + D0[1][1]*fA[0][3];
      v[1] = D0[0][2]*fA[1][0] + D0[0][3]*fA[1][1] + D0[1][2]*fA[1][2] + D0[1][3]*fA[1][3];
      v[2] = D1[0][0]*fA[2][0] + D1[0][1]*fA[2][1] + D1[1][0]*fA[2][2] + D1[1][1]*fA[2][3];
      v[3] = D1[0][2]*fA[3][0] + D1[0][3]*fA[3][1] + D1[1][2]*fA[3][2] + D1[1][3]*fA[3][3];
#pragma unroll
      for (int i = 0; i < 4; i++) {
        v[i] += __shfl_xor_sync(0xffffffffu, v[i], 1);
        v[i] += __shfl_xor_sync(0xffffffffu, v[i], 2);
      }
      if (q == 0) {
#pragma unroll
        for (int i = 0; i < 4; i++) {
          const float* E = sm + S_EB + el[i]*10;
          int dd = reinterpret_cast<const int*>(E)[9];
          if (mode == 0) {
            atomicAdd(p.out + (size_t)dd*64 + c*4, v[i]);
          } else {
            float* o = p.out + (size_t)dd*64 + c*4;
            atomicAdd(o + 1, v[i]*E[3]);
            atomicAdd(o + 2, v[i]*E[4]);
            atomicAdd(o + 3, v[i]*E[5]);
          }
        }
      }
    }
  };

  float4 wreg[8];

  stage_mlp(0, S_MLPA);
  __syncthreads();

  // ---- chunk 0: pair00 (b00 folded) -> deg0 ----
  w3load(g_W3F, wreg);
  do_radial(S_MLPA, true);
  w3store(wreg);
  __syncthreads();
  chunk_vec(0);
  stage_mlp(1, S_MLPB);
  w3load(g_W3F + 8192, wreg);
  __syncthreads();

  // ---- chunk 1: pair01 -> deg1 (x b01) ----
  do_radial(S_MLPB, false);
  w3store(wreg);
  __syncthreads();
  chunk_vec(1);
  stage_mlp(2, S_MLPA);
  w3load(g_W3F + 16384, wreg);
  __syncthreads();

  // ---- chunk 2: pair10 -> deg0; t1 precomputed into S_F0 ----
  do_radial(S_MLPA, false);
  {
    int half = t & 1, kh = half*8;
    const float* EB = sm + S_EB + el2*10;
    float g0 = EB[6], g1 = EB[7], g2 = EB[8];
    const float* f1 = sm + S_F1 + el2*48 + kh*3;
    float* t1 = sm + S_F0 + el2*16 + kh;
#pragma unroll
    for (int j = 0; j < 8; j++)
      t1[j] = f1[j*3]*g0 + f1[j*3+1]*g1 + f1[j*3+2]*g2;
  }
  w3store(wreg);
  __syncthreads();
  chunk_vec(0);
  stage_mlp(3, S_MLPB);
  w3load(g_W3F + 24576, wreg);
  __syncthreads();

  // ---- chunks 3..5: pair11 (f = 0,1,2) -> deg1 ----
  do_radial(S_MLPB, false);
  w3store(wreg);
  __syncthreads();
  {
    uint32_t A0[4][4], A1[4][4];
    loadA2(A0, A1);
    // f1 for 4 edges x 4 kf slots x 3 components
    float g[4][4][3];
    int kfs[4] = {2*q, 2*q + 1, 2*q + 8, 2*q + 9};
#pragma unroll
    for (int i = 0; i < 4; i++)
#pragma unroll
      for (int s2 = 0; s2 < 4; s2++)
#pragma unroll
        for (int k3 = 0; k3 < 3; k3++)
          g[i][s2][k3] = sm[S_F1 + el[i]*48 + kfs[s2]*3 + k3];
#pragma unroll 1
    for (int f = 0; f < 3; f++) {
#pragma unroll 1
      for (int cl = 0; cl < 8; cl++) {
        int nt0 = wn*16 + cl*2;
        float D0[2][4], D1[2][4];
        mma_cl(A0, A1, nt0, D0, D1);
        int c = wn*8 + cl;
        float s[4][3];
#pragma unroll
        for (int k3 = 0; k3 < 3; k3++) {
          s[0][k3] = D0[0][0]*g[0][0][k3] + D0[0][1]*g[0][1][k3] + D0[1][0]*g[0][2][k3] + D0[1][1]*g[0][3][k3];
          s[1][k3] = D0[0][2]*g[1][0][k3] + D0[0][3]*g[1][1][k3] + D0[1][2]*g[1][2][k3] + D0[1][3]*g[1][3][k3];
          s[2][k3] = D1[0][0]*g[2][0][k3] + D1[0][1]*g[2][1][k3] + D1[1][0]*g[2][2][k3] + D1[1][1]*g[2][3][k3];
          s[3][k3] = D1[0][2]*g[3][0][k3] + D1[0][3]*g[3][1][k3] + D1[1][2]*g[3][2][k3] + D1[1][3]*g[3][3][k3];
        }
#pragma unroll
        for (int i = 0; i < 4; i++)
#pragma unroll
          for (int k3 = 0; k3 < 3; k3++) {
            s[i][k3] += __shfl_xor_sync(0xffffffffu, s[i][k3], 1);
            s[i][k3] += __shfl_xor_sync(0xffffffffu, s[i][k3], 2);
          }
        if (q == 0) {
#pragma unroll
          for (int i = 0; i < 4; i++) {
            const float* B = sm + S_B11 + el[i]*27 + f*3;   // B[i3*9 + f*3 + o]
            int dd = reinterpret_cast<const int*>(sm + S_EB + el[i]*10)[9];
            float* o = p.out + (size_t)dd*64 + c*4;
            atomicAdd(o + 1, s[i][0]*B[0] + s[i][1]*B[9]  + s[i][2]*B[18]);
            atomicAdd(o + 2, s[i][0]*B[1] + s[i][1]*B[10] + s[i][2]*B[19]);
            atomicAdd(o + 3, s[i][0]*B[2] + s[i][1]*B[11] + s[i][2]*B[20]);
          }
        }
      }
      if (f < 2) {
        w3load(g_W3F + (4 + f)*8192, wreg);
        __syncthreads();
        w3store(wreg);
        __syncthreads();
      }
    }
  }
}

// ---------- scalar tail (E % 128 edges; weights from gmem) ----------
__device__ void radial_g(const float* w1, const float* b1, const float* w2,
                         const float* b2, float ei0, float ei1, float h2[32]) {
  float h1[32];
  for (int m = 0; m < 32; m++)
    h1[m] = fmaxf(fmaf(ei0, w1[m], fmaf(ei1, w1[32+m], b1[m])), 0.f);
  for (int m = 0; m < 32; m++) {
    float a = b2[m];
    for (int n = 0; n < 32; n++) a = fmaf(h1[n], w2[n*32 + m], a);
    h2[m] = fmaxf(a, 0.f);
  }
}

__global__ void convTail(P p, int e0) {
  int e = e0 + threadIdx.x;
  if (e >= p.E) return;
  int s = p.src[e], d = p.dst[e];
  float ei0 = p.edge_inv[2*e], ei1 = p.edge_inv[2*e+1];
  float f0[16], f1[48];
  for (int i = 0; i < 16; i++) f0[i] = p.feat0[(size_t)s*16 + i];
  for (int i = 0; i < 48; i++) f1[i] = p.feat1[(size_t)s*48 + i];
  float h2[32], out0[16], o1[48];
  for (int c = 0; c < 16; c++) out0[c] = 0.f;
  for (int j = 0; j < 48; j++) o1[j] = 0.f;
  radial_g(p.w1[0], p.bb1[0], p.w2[0], p.bb2[0], ei0, ei1, h2);
  float bv = p.b00[e];
  for (int c = 0; c < 16; c++) {
    float v = 0.f;
    for (int k = 0; k < 16; k++) {
      float rw = 0.f;
      for (int m = 0; m < 32; m++) rw = fmaf(h2[m], p.w3[0][m*256 + c*16 + k], rw);
      v = fmaf(rw, f0[k], v);
    }
    out0[c] += v * bv;
  }
  radial_g(p.w1[1], p.bb1[1], p.w2[1], p.bb2[1], ei0, ei1, h2);
  float q0 = p.b01[e*3], q1 = p.b01[e*3+1], q2 = p.b01[e*3+2];
  for (int c = 0; c < 16; c++) {
    float v = 0.f;
    for (int k = 0; k < 16; k++) {
      float rw = 0.f;
      for (int m = 0; m < 32; m++) rw = fmaf(h2[m], p.w3[1][m*256 + c*16 + k], rw);
      v = fmaf(rw, f0[k], v);
    }
    o1[c*3] += v*q0; o1[c*3+1] += v*q1; o1[c*3+2] += v*q2;
  }
  radial_g(p.w1[2], p.bb1[2], p.w2[2], p.bb2[2], ei0, ei1, h2);
  float g0 = p.b10[e*3], g1 = p.b10[e*3+1], g2 = p.b10[e*3+2];
  for (int c = 0; c < 16; c++) {
    float v = 0.f;
    for (int k = 0; k < 16; k++) {
      float rw = 0.f;
      for (int m = 0; m < 32; m++) rw = fmaf(h2[m], p.w3[2][m*256 + c*16 + k], rw);
      v = fmaf(rw, f1[k*3]*g0 + f1[k*3+1]*g1 + f1[k*3+2]*g2, v);
    }
    out0[c] += v;
  }
  radial_g(p.w1[3], p.bb1[3], p.w2[3], p.bb2[3], ei0, ei1, h2);
  for (int c = 0; c < 16; c++) {
    for (int k = 0; k < 16; k++) {
      for (int f = 0; f < 3; f++) {
        float rw = 0.f;
        for (int m = 0; m < 32; m++) rw = fmaf(h2[m], p.w3[3][m*768 + c*48 + k*3 + f], rw);
        for (int o = 0; o < 3; o++) {
          float tt = f1[k*3]*p.b11[(size_t)e*27 + f*3 + o]
                   + f1[k*3+1]*p.b11[(size_t)e*27 + 9 + f*3 + o]
                   + f1[k*3+2]*p.b11[(size_t)e*27 + 18 + f*3 + o];
          o1[c*3+o] = fmaf(rw, tt, o1[c*3+o]);
        }
      }
    }
  }
  float* outp = p.out + (size_t)d * 64;
  for (int c = 0; c < 16; c++) {
    atomicAdd(outp + c*4,     out0[c]);
    atomicAdd(outp + c*4 + 1, o1[c*3]);
    atomicAdd(outp + c*4 + 2, o1[c*3+1]);
    atomicAdd(outp + c*4 + 3, o1[c*3+2]);
  }
}

}  // namespace

extern "C" void kernel_launch(void* const* d_in, const int* in_sizes, int n_in,
                              void* d_out, int out_size) {
  P p{};
  p.feat0    = (const float*)d_in[0];
  p.feat1    = (const float*)d_in[1];
  p.edge_inv = (const float*)d_in[2];
  p.src      = (const int*)d_in[3];
  p.dst      = (const int*)d_in[4];
  p.b00 = (const float*)d_in[5];
  p.b01 = (const float*)d_in[6];
  p.b10 = (const float*)d_in[7];
  p.b11 = (const float*)d_in[8];
  const int base[4] = {9, 14, 19, 24};   // 00, 01, 10, 11
  for (int pr = 0; pr < 4; pr++) {
    p.w1[pr]  = (const float*)d_in[base[pr]];
    p.bb1[pr] = (const float*)d_in[base[pr]+1];
    p.w2[pr]  = (const float*)d_in[base[pr]+2];
    p.bb2[pr] = (const float*)d_in[base[pr]+3];
    p.w3[pr]  = (const float*)d_in[base[pr]+4];
  }
  p.out = (float*)d_out;
  p.E = in_sizes[3];

  static bool attr_done = false;
  if (!attr_done) {
    cudaFuncSetAttribute(convFused, cudaFuncAttributeMaxDynamicSharedMemorySize,
                         S_TOT * 4);
    attr_done = true;
  }

  int nblk = (out_size + 255) / 256;
  if (nblk < 192) nblk = 192;
  prolog<<<nblk, 256>>>(p, out_size);

  int nfull = p.E / 128;
  if (nfull > 0) convFused<<<nfull, 256, S_TOT * 4>>>(p);
  int tail = p.E - nfull * 128;
  if (tail > 0) convTail<<<1, tail>>>(p, nfull * 128);
}

// round 16
// speedup vs baseline: 1.3581x; 1.1315x over previous
#include <cuda_runtime.h>
#include <cstdint>

namespace {
using u64 = unsigned long long;

__device__ __forceinline__ u64 pk(float x) {
  u64 d; unsigned xi = __float_as_uint(x);
  asm("mov.b64 %0, {%1, %1};" : "=l"(d) : "r"(xi));
  return d;
}
__device__ __forceinline__ u64 ffma2(u64 a, u64 b, u64 c) {
  u64 d;
  asm("fma.rn.f32x2 %0, %1, %2, %3;" : "=l"(d) : "l"(a), "l"(b), "l"(c));
  return d;
}
__device__ __forceinline__ float2 unpk(u64 d) {
  unsigned lo, hi;
  asm("mov.b64 {%0, %1}, %2;" : "=r"(lo), "=r"(hi) : "l"(d));
  return make_float2(__uint_as_float(lo), __uint_as_float(hi));
}
__device__ __forceinline__ uint32_t cvt_tf32(float x) {
  uint32_t r;
  asm("cvt.rna.tf32.f32 %0, %1;" : "=r"(r) : "f"(x));
  return r;
}
__device__ __forceinline__ void mma_tf32(float d[4], const uint32_t a[4],
                                         uint32_t b0, uint32_t b1) {
  asm volatile(
      "mma.sync.aligned.m16n8k8.row.col.f32.tf32.tf32.f32 "
      "{%0,%1,%2,%3}, {%4,%5,%6,%7}, {%8,%9}, {%0,%1,%2,%3};"
      : "+f"(d[0]), "+f"(d[1]), "+f"(d[2]), "+f"(d[3])
      : "r"(a[0]), "r"(a[1]), "r"(a[2]), "r"(a[3]), "r"(b0), "r"(b1));
}

struct P {
  const float *feat0, *feat1, *edge_inv;
  const int *src, *dst;
  const float *b00, *b01, *b10, *b11;
  const float *w1[4], *bb1[4], *w2[4], *bb2[4], *w3[4];  // 00,01,10,11
  float* out;
  int E;
};

// All 6 W3 chunks in mma fragment-major layout, tf32-pre-rounded.
__device__ float g_W3F[49152];

__global__ void prolog(P p, int nout) {
  int i = blockIdx.x * 256 + threadIdx.x;
  if (i < nout) p.out[i] = 0.f;
  if (i < 49152) {
    int chunk = i >> 13;
    int il = i & 8191;
    int sel = il & 1;
    int ktb = (il >> 1) & 1;
    int lane = (il >> 2) & 31;
    int nt = (il >> 7) & 31;
    int kt2 = (il >> 12) & 1;
    int q = lane & 3, r = lane >> 2;
    int kdim = (kt2*2 + ktb)*8 + sel*4 + q;
    int n = nt*8 + r;
    int c = n >> 4, k = n & 15;
    float v;
    if (chunk < 3) {
      const float* w3 = (chunk == 0) ? p.w3[0] : ((chunk == 1) ? p.w3[1] : p.w3[2]);
      v = w3[kdim*256 + c*16 + k];
    } else {
      v = p.w3[3][kdim*768 + c*48 + k*3 + (chunk - 3)];
    }
    g_W3F[i] = __uint_as_float(cvt_tf32(v));
  }
}

// smem float offsets
constexpr int S_F0  = 0;        // [128][16]  f0; reused as t1 before pair10
constexpr int S_F1  = 2048;     // [128][48]
constexpr int S_EB  = 8192;     // [128][10]
constexpr int S_B11 = 9472;     // [128][27]
constexpr int S_H2  = 12928;    // [128][36] padded rows (tf32 bits)
constexpr int S_W3  = 17536;    // [8192]  fragment-major B tile
constexpr int S_MLPA= 25856;    // 1152
constexpr int S_MLPB= 27008;    // 1152
constexpr int S_TOT = 28160;    // 112640 B (x2 CTA = 225 KB)

__device__ __forceinline__ void radial_half(const float* __restrict__ mlp,
                                            float ei0, float ei1, int mhalf,
                                            float h2[16]) {
  const float* w1 = mlp; const float* b1 = mlp + 64;
  const float* w2 = mlp + 96; const float* b2 = mlp + 1120;
  float h1[32];
#pragma unroll
  for (int j = 0; j < 32; j++)
    h1[j] = fmaxf(fmaf(ei0, w1[j], fmaf(ei1, w1[32 + j], b1[j])), 0.f);
  u64 acc[8];
  const ulonglong2* b2p = reinterpret_cast<const ulonglong2*>(b2 + mhalf);
#pragma unroll
  for (int j = 0; j < 4; j++) {
    ulonglong2 b = b2p[j];
    acc[j*2] = b.x; acc[j*2+1] = b.y;
  }
#pragma unroll
  for (int n = 0; n < 32; n++) {
    u64 h = pk(h1[n]);
    const ulonglong2* wrow = reinterpret_cast<const ulonglong2*>(w2 + n*32 + mhalf);
    ulonglong2 p0 = wrow[0], p1 = wrow[1], p2 = wrow[2], p3 = wrow[3];
    acc[0] = ffma2(h, p0.x, acc[0]); acc[1] = ffma2(h, p0.y, acc[1]);
    acc[2] = ffma2(h, p1.x, acc[2]); acc[3] = ffma2(h, p1.y, acc[3]);
    acc[4] = ffma2(h, p2.x, acc[4]); acc[5] = ffma2(h, p2.y, acc[5]);
    acc[6] = ffma2(h, p3.x, acc[6]); acc[7] = ffma2(h, p3.y, acc[7]);
  }
#pragma unroll
  for (int j = 0; j < 8; j++) {
    float2 q = unpk(acc[j]);
    h2[2*j]   = fmaxf(q.x, 0.f);
    h2[2*j+1] = fmaxf(q.y, 0.f);
  }
}

// Guard-free main kernel: every block covers 128 valid edges.
// Warp tiling: warp w -> edge quarter we = w>>1 (32 edges), n-half wn = w&1.
// Lane (r,q) OWNS edge ebase + r + q*8 for output accumulation/atomics.
__global__ void __launch_bounds__(256, 2) convFused(P p) {
  extern __shared__ float sm[];
  int t = threadIdx.x;
  int eb = blockIdx.x * 128;
  int w = t >> 5, lane = t & 31;
  int r = lane >> 2, q = lane & 3;
  int we = w >> 1, wn = w & 1;
  int ebase = we * 32;
  int elq = ebase + r + q*8;          // owned edge (local)
  int el2 = t >> 1, mhalf = (t & 1) * 16;

  // ---------- stage per-edge data ----------
  if (t < 128) {
    int e = eb + t;
    float* EB = sm + S_EB + t*10;
    EB[0] = p.edge_inv[2*e];
    EB[1] = p.edge_inv[2*e+1];
    EB[2] = p.b00[e];
    EB[3] = p.b01[3*e]; EB[4] = p.b01[3*e+1]; EB[5] = p.b01[3*e+2];
    EB[6] = p.b10[3*e]; EB[7] = p.b10[3*e+1]; EB[8] = p.b10[3*e+2];
    reinterpret_cast<int*>(EB)[9] = p.dst[e];
  }
  {
    int half = t & 1;
    int e = eb + el2;
    int s = p.src[e];
    const float4* f0g = reinterpret_cast<const float4*>(p.feat0 + (size_t)s*16);
    float4* f0s = reinterpret_cast<float4*>(sm + S_F0 + el2*16);
    f0s[half*2+0] = f0g[half*2+0];
    f0s[half*2+1] = f0g[half*2+1];
    const float4* f1g = reinterpret_cast<const float4*>(p.feat1 + (size_t)s*48);
    float4* f1s = reinterpret_cast<float4*>(sm + S_F1 + el2*48);
#pragma unroll
    for (int qq = 0; qq < 6; qq++) f1s[half*6+qq] = f1g[half*6+qq];
    const float* bg = p.b11 + (size_t)e*27;
    float* bs = sm + S_B11 + el2*27;
    for (int qq = half; qq < 27; qq += 2) bs[qq] = bg[qq];
  }

  auto stage_mlp = [&](int pr, int off) {
    float* d = sm + off;
    if (t < 64) d[t] = p.w1[pr][t];
    else if (t < 96) d[64 + (t-64)] = p.bb1[pr][t-64];
    else if (t < 128) d[1120 + (t-96)] = p.bb2[pr][t-96];
    for (int i = t; i < 1024; i += 256) d[96 + i] = p.w2[pr][i];
  };
  auto do_radial = [&](int off, bool fold) {
    const float* EB = sm + S_EB + el2*10;
    float h2[16];
    radial_half(sm + off, EB[0], EB[1], mhalf, h2);
    float sc = fold ? EB[2] : 1.f;
#pragma unroll
    for (int j = 0; j < 16; j++)
      sm[S_H2 + el2*36 + mhalf + j] = __uint_as_float(cvt_tf32(h2[j] * sc));
  };
  auto w3load = [&](const float* __restrict__ g, float4 rr[8]) {
    const float4* s4 = reinterpret_cast<const float4*>(g);
#pragma unroll
    for (int qq = 0; qq < 8; qq++) rr[qq] = s4[t + 256*qq];
  };
  auto w3store = [&](const float4 rr[8]) {
    float4* d = reinterpret_cast<float4*>(sm + S_W3);
#pragma unroll
    for (int qq = 0; qq < 8; qq++) d[t + 256*qq] = rr[qq];
  };
  auto loadA2 = [&](uint32_t A0[4][4], uint32_t A1[4][4]) {
    int e0 = ebase + r, e1 = e0 + 8, e2 = e0 + 16, e3 = e0 + 24;
#pragma unroll
    for (int kt = 0; kt < 4; kt++) {
      A0[kt][0] = __float_as_uint(sm[S_H2 + e0*36 + kt*8 + q]);
      A0[kt][1] = __float_as_uint(sm[S_H2 + e1*36 + kt*8 + q]);
      A0[kt][2] = __float_as_uint(sm[S_H2 + e0*36 + kt*8 + q + 4]);
      A0[kt][3] = __float_as_uint(sm[S_H2 + e1*36 + kt*8 + q + 4]);
      A1[kt][0] = __float_as_uint(sm[S_H2 + e2*36 + kt*8 + q]);
      A1[kt][1] = __float_as_uint(sm[S_H2 + e3*36 + kt*8 + q]);
      A1[kt][2] = __float_as_uint(sm[S_H2 + e2*36 + kt*8 + q + 4]);
      A1[kt][3] = __float_as_uint(sm[S_H2 + e3*36 + kt*8 + q + 4]);
    }
  };

  float fAreg[4][4];      // per-edge vec (f0 or t1) cached in regs
  float o1acc[8][3];      // deg-1 accumulator for OWNED edge (per c-col cl)
  auto load_vec = [&]() {
#pragma unroll
    for (int i = 0; i < 4; i++) {
      int eli = ebase + r + i*8;
      fAreg[i][0] = sm[S_F0 + eli*16 + 2*q];
      fAreg[i][1] = sm[S_F0 + eli*16 + 2*q + 1];
      fAreg[i][2] = sm[S_F0 + eli*16 + 2*q + 8];
      fAreg[i][3] = sm[S_F0 + eli*16 + 2*q + 9];
    }
  };

  // mma over 2 nt for both m-tiles
  auto mma_cl2 = [&](const uint32_t A0[4][4], const uint32_t A1[4][4], int nt0,
                     float D0[2][4], float D1[2][4]) {
#pragma unroll
    for (int i = 0; i < 2; i++)
#pragma unroll
      for (int j = 0; j < 4; j++) { D0[i][j] = 0.f; D1[i][j] = 0.f; }
    const float4* F = reinterpret_cast<const float4*>(sm + S_W3);
    float4 va1 = F[nt0*32 + lane];
    float4 va2 = F[1024 + nt0*32 + lane];
    float4 vb1 = F[(nt0+1)*32 + lane];
    float4 vb2 = F[1024 + (nt0+1)*32 + lane];
    mma_tf32(D0[0], A0[0], __float_as_uint(va1.x), __float_as_uint(va1.y));
    mma_tf32(D0[0], A0[1], __float_as_uint(va1.z), __float_as_uint(va1.w));
    mma_tf32(D0[0], A0[2], __float_as_uint(va2.x), __float_as_uint(va2.y));
    mma_tf32(D0[0], A0[3], __float_as_uint(va2.z), __float_as_uint(va2.w));
    mma_tf32(D0[1], A0[0], __float_as_uint(vb1.x), __float_as_uint(vb1.y));
    mma_tf32(D0[1], A0[1], __float_as_uint(vb1.z), __float_as_uint(vb1.w));
    mma_tf32(D0[1], A0[2], __float_as_uint(vb2.x), __float_as_uint(vb2.y));
    mma_tf32(D0[1], A0[3], __float_as_uint(vb2.z), __float_as_uint(vb2.w));
    mma_tf32(D1[0], A1[0], __float_as_uint(va1.x), __float_as_uint(va1.y));
    mma_tf32(D1[0], A1[1], __float_as_uint(va1.z), __float_as_uint(va1.w));
    mma_tf32(D1[0], A1[2], __float_as_uint(va2.x), __float_as_uint(va2.y));
    mma_tf32(D1[0], A1[3], __float_as_uint(va2.z), __float_as_uint(va2.w));
    mma_tf32(D1[1], A1[0], __float_as_uint(vb1.x), __float_as_uint(vb1.y));
    mma_tf32(D1[1], A1[1], __float_as_uint(vb1.z), __float_as_uint(vb1.w));
    mma_tf32(D1[1], A1[2], __float_as_uint(vb2.x), __float_as_uint(vb2.y));
    mma_tf32(D1[1], A1[3], __float_as_uint(vb2.z), __float_as_uint(vb2.w));
  };

  // pairs 00/01/10: vec-dot epilogue. mode 0 -> direct deg0 atomic (lane-owned);
  // mode 1 -> initialize o1acc with v * b01.
  auto chunk_vec = [&](int mode) {
    uint32_t A0[4][4], A1[4][4];
    loadA2(A0, A1);
    const float* Eq = sm + S_EB + elq*10;
#pragma unroll 1
    for (int cl = 0; cl < 8; cl++) {
      int nt0 = wn*16 + cl*2;
      float D0[2][4], D1[2][4];
      mma_cl2(A0, A1, nt0, D0, D1);
      int c = wn*8 + cl;
      float v[4];
      v[0] = D0[0][0]*fAreg[0][0] + D0[0][1]*fAreg[0][1] + D0[1][0]*fAreg[0][2] + D0[1][1]*fAreg[0][3];
      v[1] = D0[0][2]*fAreg[1][0] + D0[0][3]*fAreg[1][1] + D0[1][2]*fAreg[1][2] + D0[1][3]*fAreg[1][3];
      v[2] = D1[0][0]*fAreg[2][0] + D1[0][1]*fAreg[2][1] + D1[1][0]*fAreg[2][2] + D1[1][1]*fAreg[2][3];
      v[3] = D1[0][2]*fAreg[3][0] + D1[0][3]*fAreg[3][1] + D1[1][2]*fAreg[3][2] + D1[1][3]*fAreg[3][3];
#pragma unroll
      for (int i = 0; i < 4; i++) {
        v[i] += __shfl_xor_sync(0xffffffffu, v[i], 1);
        v[i] += __shfl_xor_sync(0xffffffffu, v[i], 2);
      }
      float vq = (q == 0) ? v[0] : (q == 1) ? v[1] : (q == 2) ? v[2] : v[3];
      if (mode == 0) {
        int dq = reinterpret_cast<const int*>(Eq)[9];
        atomicAdd(p.out + (size_t)dq*64 + c*4, vq);
      } else {
        o1acc[cl][0] = vq * Eq[3];
        o1acc[cl][1] = vq * Eq[4];
        o1acc[cl][2] = vq * Eq[5];
      }
    }
  };

  float4 wreg[8];

  stage_mlp(0, S_MLPA);
  __syncthreads();

  // ---- chunk 0: pair00 (b00 folded) -> deg0 ----
  w3load(g_W3F, wreg);
  do_radial(S_MLPA, true);
  w3store(wreg);
  __syncthreads();
  load_vec();            // f0
  chunk_vec(0);
  stage_mlp(1, S_MLPB);
  w3load(g_W3F + 8192, wreg);
  __syncthreads();

  // ---- chunk 1: pair01 -> o1acc (no atomics) ----
  do_radial(S_MLPB, false);
  w3store(wreg);
  __syncthreads();
  chunk_vec(1);          // fAreg still f0
  stage_mlp(2, S_MLPA);
  w3load(g_W3F + 16384, wreg);
  __syncthreads();

  // ---- chunk 2: pair10 -> deg0; t1 precomputed into S_F0 ----
  do_radial(S_MLPA, false);
  {
    int half = t & 1, kh = half*8;
    const float* EB = sm + S_EB + el2*10;
    float g0 = EB[6], g1 = EB[7], g2 = EB[8];
    const float* f1 = sm + S_F1 + el2*48 + kh*3;
    float* t1 = sm + S_F0 + el2*16 + kh;
#pragma unroll
    for (int j = 0; j < 8; j++)
      t1[j] = f1[j*3]*g0 + f1[j*3+1]*g1 + f1[j*3+2]*g2;
  }
  w3store(wreg);
  __syncthreads();
  load_vec();            // t1
  chunk_vec(0);
  stage_mlp(3, S_MLPB);
  w3load(g_W3F + 24576, wreg);
  __syncthreads();

  // ---- chunks 3..5: pair11 (f = 0,1,2) -> o1acc; two m-tile passes ----
  do_radial(S_MLPB, false);
  w3store(wreg);
  __syncthreads();
  {
    int passq = q >> 1, iq = q & 1;
#pragma unroll 1
    for (int f = 0; f < 3; f++) {
      float Bq[9];   // basis of OWNED edge: Bq[k3*3+o] = B[k3*9 + f*3 + o]
#pragma unroll
      for (int k3 = 0; k3 < 3; k3++)
#pragma unroll
        for (int o = 0; o < 3; o++)
          Bq[k3*3+o] = sm[S_B11 + elq*27 + k3*9 + f*3 + o];
#pragma unroll 1
      for (int pass = 0; pass < 2; pass++) {
        int ea = ebase + pass*16 + r, ebg = ea + 8;
        uint32_t A[4][4];
#pragma unroll
        for (int kt = 0; kt < 4; kt++) {
          A[kt][0] = __float_as_uint(sm[S_H2 + ea*36 + kt*8 + q]);
          A[kt][1] = __float_as_uint(sm[S_H2 + ebg*36 + kt*8 + q]);
          A[kt][2] = __float_as_uint(sm[S_H2 + ea*36 + kt*8 + q + 4]);
          A[kt][3] = __float_as_uint(sm[S_H2 + ebg*36 + kt*8 + q + 4]);
        }
        float gp[2][4][3];
#pragma unroll
        for (int s2 = 0; s2 < 4; s2++) {
          int kf = 2*q + ((s2 < 2) ? s2 : (6 + s2));   // 2q, 2q+1, 2q+8, 2q+9
#pragma unroll
          for (int k3 = 0; k3 < 3; k3++) {
            gp[0][s2][k3] = sm[S_F1 + ea*48 + kf*3 + k3];
            gp[1][s2][k3] = sm[S_F1 + ebg*48 + kf*3 + k3];
          }
        }
#pragma unroll 1
        for (int cl = 0; cl < 8; cl++) {
          int nt0 = wn*16 + cl*2;
          float D[2][4];
#pragma unroll
          for (int i = 0; i < 2; i++)
#pragma unroll
            for (int j = 0; j < 4; j++) D[i][j] = 0.f;
          const float4* F = reinterpret_cast<const float4*>(sm + S_W3);
          float4 va1 = F[nt0*32 + lane];
          float4 va2 = F[1024 + nt0*32 + lane];
          float4 vb1 = F[(nt0+1)*32 + lane];
          float4 vb2 = F[1024 + (nt0+1)*32 + lane];
          mma_tf32(D[0], A[0], __float_as_uint(va1.x), __float_as_uint(va1.y));
          mma_tf32(D[0], A[1], __float_as_uint(va1.z), __float_as_uint(va1.w));
          mma_tf32(D[0], A[2], __float_as_uint(va2.x), __float_as_uint(va2.y));
          mma_tf32(D[0], A[3], __float_as_uint(va2.z), __float_as_uint(va2.w));
          mma_tf32(D[1], A[0], __float_as_uint(vb1.x), __float_as_uint(vb1.y));
          mma_tf32(D[1], A[1], __float_as_uint(vb1.z), __float_as_uint(vb1.w));
          mma_tf32(D[1], A[2], __float_as_uint(vb2.x), __float_as_uint(vb2.y));
          mma_tf32(D[1], A[3], __float_as_uint(vb2.z), __float_as_uint(vb2.w));
          float s0[3], s1[3];
#pragma unroll
          for (int k3 = 0; k3 < 3; k3++) {
            s0[k3] = D[0][0]*gp[0][0][k3] + D[0][1]*gp[0][1][k3] + D[1][0]*gp[0][2][k3] + D[1][1]*gp[0][3][k3];
            s1[k3] = D[0][2]*gp[1][0][k3] + D[0][3]*gp[1][1][k3] + D[1][2]*gp[1][2][k3] + D[1][3]*gp[1][3][k3];
            s0[k3] += __shfl_xor_sync(0xffffffffu, s0[k3], 1);
            s0[k3] += __shfl_xor_sync(0xffffffffu, s0[k3], 2);
            s1[k3] += __shfl_xor_sync(0xffffffffu, s1[k3], 1);
            s1[k3] += __shfl_xor_sync(0xffffffffu, s1[k3], 2);
          }
          if (pass == passq) {
            float sq0 = iq ? s1[0] : s0[0];
            float sq1 = iq ? s1[1] : s0[1];
            float sq2 = iq ? s1[2] : s0[2];
            o1acc[cl][0] += sq0*Bq[0] + sq1*Bq[3] + sq2*Bq[6];
            o1acc[cl][1] += sq0*Bq[1] + sq1*Bq[4] + sq2*Bq[7];
            o1acc[cl][2] += sq0*Bq[2] + sq1*Bq[5] + sq2*Bq[8];
          }
        }
      }
      if (f < 2) {
        w3load(g_W3F + (4 + f)*8192, wreg);
        __syncthreads();
        w3store(wreg);
        __syncthreads();
      }
    }
  }

  // ---- flush deg-1 accumulator (lane-owned edge): 24 atomic instrs ----
  {
    int dq = reinterpret_cast<const int*>(sm + S_EB + elq*10)[9];
    float* ob = p.out + (size_t)dq*64;
#pragma unroll 1
    for (int cl = 0; cl < 8; cl++) {
      int c = wn*8 + cl;
      atomicAdd(ob + c*4 + 1, o1acc[cl][0]);
      atomicAdd(ob + c*4 + 2, o1acc[cl][1]);
      atomicAdd(ob + c*4 + 3, o1acc[cl][2]);
    }
  }
}

// ---------- scalar tail (E % 128 edges; weights from gmem) ----------
__device__ void radial_g(const float* w1, const float* b1, const float* w2,
                         const float* b2, float ei0, float ei1, float h2[32]) {
  float h1[32];
  for (int m = 0; m < 32; m++)
    h1[m] = fmaxf(fmaf(ei0, w1[m], fmaf(ei1, w1[32+m], b1[m])), 0.f);
  for (int m = 0; m < 32; m++) {
    float a = b2[m];
    for (int n = 0; n < 32; n++) a = fmaf(h1[n], w2[n*32 + m], a);
    h2[m] = fmaxf(a, 0.f);
  }
}

__global__ void convTail(P p, int e0) {
  int e = e0 + threadIdx.x;
  if (e >= p.E) return;
  int s = p.src[e], d = p.dst[e];
  float ei0 = p.edge_inv[2*e], ei1 = p.edge_inv[2*e+1];
  float f0[16], f1[48];
  for (int i = 0; i < 16; i++) f0[i] = p.feat0[(size_t)s*16 + i];
  for (int i = 0; i < 48; i++) f1[i] = p.feat1[(size_t)s*48 + i];
  float h2[32], out0[16], o1[48];
  for (int c = 0; c < 16; c++) out0[c] = 0.f;
  for (int j = 0; j < 48; j++) o1[j] = 0.f;
  radial_g(p.w1[0], p.bb1[0], p.w2[0], p.bb2[0], ei0, ei1, h2);
  float bv = p.b00[e];
  for (int c = 0; c < 16; c++) {
    float v = 0.f;
    for (int k = 0; k < 16; k++) {
      float rw = 0.f;
      for (int m = 0; m < 32; m++) rw = fmaf(h2[m], p.w3[0][m*256 + c*16 + k], rw);
      v = fmaf(rw, f0[k], v);
    }
    out0[c] += v * bv;
  }
  radial_g(p.w1[1], p.bb1[1], p.w2[1], p.bb2[1], ei0, ei1, h2);
  float q0 = p.b01[e*3], q1 = p.b01[e*3+1], q2 = p.b01[e*3+2];
  for (int c = 0; c < 16; c++) {
    float v = 0.f;
    for (int k = 0; k < 16; k++) {
      float rw = 0.f;
      for (int m = 0; m < 32; m++) rw = fmaf(h2[m], p.w3[1][m*256 + c*16 + k], rw);
      v = fmaf(rw, f0[k], v);
    }
    o1[c*3] += v*q0; o1[c*3+1] += v*q1; o1[c*3+2] += v*q2;
  }
  radial_g(p.w1[2], p.bb1[2], p.w2[2], p.bb2[2], ei0, ei1, h2);
  float g0 = p.b10[e*3], g1 = p.b10[e*3+1], g2 = p.b10[e*3+2];
  for (int c = 0; c < 16; c++) {
    float v = 0.f;
    for (int k = 0; k < 16; k++) {
      float rw = 0.f;
      for (int m = 0; m < 32; m++) rw = fmaf(h2[m], p.w3[2][m*256 + c*16 + k], rw);
      v = fmaf(rw, f1[k*3]*g0 + f1[k*3+1]*g1 + f1[k*3+2]*g2, v);
    }
    out0[c] += v;
  }
  radial_g(p.w1[3], p.bb1[3], p.w2[3], p.bb2[3], ei0, ei1, h2);
  for (int c = 0; c < 16; c++) {
    for (int k = 0; k < 16; k++) {
      for (int f = 0; f < 3; f++) {
        float rw = 0.f;
        for (int m = 0; m < 32; m++) rw = fmaf(h2[m], p.w3[3][m*768 + c*48 + k*3 + f], rw);
        for (int o = 0; o < 3; o++) {
          float tt = f1[k*3]*p.b11[(size_t)e*27 + f*3 + o]
                   + f1[k*3+1]*p.b11[(size_t)e*27 + 9 + f*3 + o]
                   + f1[k*3+2]*p.b11[(size_t)e*27 + 18 + f*3 + o];
          o1[c*3+o] = fmaf(rw, tt, o1[c*3+o]);
        }
      }
    }
  }
  float* outp = p.out + (size_t)d * 64;
  for (int c = 0; c < 16; c++) {
    atomicAdd(outp + c*4,     out0[c]);
    atomicAdd(outp + c*4 + 1, o1[c*3]);
    atomicAdd(outp + c*4 + 2, o1[c*3+1]);
    atomicAdd(outp + c*4 + 3, o1[c*3+2]);
  }
}

}  // namespace

extern "C" void kernel_launch(void* const* d_in, const int* in_sizes, int n_in,
                              void* d_out, int out_size) {
  P p{};
  p.feat0    = (const float*)d_in[0];
  p.feat1    = (const float*)d_in[1];
  p.edge_inv = (const float*)d_in[2];
  p.src      = (const int*)d_in[3];
  p.dst      = (const int*)d_in[4];
  p.b00 = (const float*)d_in[5];
  p.b01 = (const float*)d_in[6];
  p.b10 = (const float*)d_in[7];
  p.b11 = (const float*)d_in[8];
  const int base[4] = {9, 14, 19, 24};   // 00, 01, 10, 11
  for (int pr = 0; pr < 4; pr++) {
    p.w1[pr]  = (const float*)d_in[base[pr]];
    p.bb1[pr] = (const float*)d_in[base[pr]+1];
    p.w2[pr]  = (const float*)d_in[base[pr]+2];
    p.bb2[pr] = (const float*)d_in[base[pr]+3];
    p.w3[pr]  = (const float*)d_in[base[pr]+4];
  }
  p.out = (float*)d_out;
  p.E = in_sizes[3];

  static bool attr_done = false;
  if (!attr_done) {
    cudaFuncSetAttribute(convFused, cudaFuncAttributeMaxDynamicSharedMemorySize,
                         S_TOT * 4);
    attr_done = true;
  }

  int nblk = (out_size + 255) / 256;
  if (nblk < 192) nblk = 192;
  prolog<<<nblk, 256>>>(p, out_size);

  int nfull = p.E / 128;
  if (nfull > 0) convFused<<<nfull, 256, S_TOT * 4>>>(p);
  int tail = p.E - nfull * 128;
  if (tail > 0) convTail<<<1, tail>>>(p, nfull * 128);
}

// round 17
// speedup vs baseline: 1.8040x; 1.3284x over previous
#include <cuda_runtime.h>
#include <cstdint>

namespace {
using u64 = unsigned long long;

__device__ __forceinline__ u64 pk(float x) {
  u64 d; unsigned xi = __float_as_uint(x);
  asm("mov.b64 %0, {%1, %1};" : "=l"(d) : "r"(xi));
  return d;
}
__device__ __forceinline__ u64 ffma2(u64 a, u64 b, u64 c) {
  u64 d;
  asm("fma.rn.f32x2 %0, %1, %2, %3;" : "=l"(d) : "l"(a), "l"(b), "l"(c));
  return d;
}
__device__ __forceinline__ float2 unpk(u64 d) {
  unsigned lo, hi;
  asm("mov.b64 {%0, %1}, %2;" : "=r"(lo), "=r"(hi) : "l"(d));
  return make_float2(__uint_as_float(lo), __uint_as_float(hi));
}
__device__ __forceinline__ uint32_t cvt_tf32(float x) {
  uint32_t r;
  asm("cvt.rna.tf32.f32 %0, %1;" : "=r"(r) : "f"(x));
  return r;
}
__device__ __forceinline__ void mma_tf32(float d[4], const uint32_t a[4],
                                         uint32_t b0, uint32_t b1) {
  asm volatile(
      "mma.sync.aligned.m16n8k8.row.col.f32.tf32.tf32.f32 "
      "{%0,%1,%2,%3}, {%4,%5,%6,%7}, {%8,%9}, {%0,%1,%2,%3};"
      : "+f"(d[0]), "+f"(d[1]), "+f"(d[2]), "+f"(d[3])
      : "r"(a[0]), "r"(a[1]), "r"(a[2]), "r"(a[3]), "r"(b0), "r"(b1));
}

struct P {
  const float *feat0, *feat1, *edge_inv;
  const int *src, *dst;
  const float *b00, *b01, *b10, *b11;
  const float *w1[4], *bb1[4], *w2[4], *bb2[4], *w3[4];  // 00,01,10,11
  float* out;
  int E;
};

// All 6 W3 chunks in mma fragment-major layout, tf32-pre-rounded.
// k-major n-ordering: GEMM column n <-> (wn = nt>>4, u = nt&15, c_l = col-in-group).
// idx = ((kt2*32 + nt)*32 + lane)*4 + ktb*2 + sel
// kdim = (kt2*2+ktb)*8 + sel*4 + (lane&3); c = (nt>>4)*8 + (lane>>2); u = nt&15
__device__ float g_W3F[49152];

__global__ void prolog(P p, int nout) {
  int i = blockIdx.x * 256 + threadIdx.x;
  if (i < nout) p.out[i] = 0.f;
  if (i < 49152) {
    int chunk = i >> 13;
    int il = i & 8191;
    int sel = il & 1;
    int ktb = (il >> 1) & 1;
    int lane = (il >> 2) & 31;
    int nt = (il >> 7) & 31;
    int kt2 = (il >> 12) & 1;
    int q = lane & 3, r = lane >> 2;
    int kdim = (kt2*2 + ktb)*8 + sel*4 + q;
    int u = nt & 15;              // feature channel (contracted in epilogue)
    int c = (nt >> 4)*8 + r;      // output channel
    float v;
    if (chunk < 3) {
      const float* w3 = (chunk == 0) ? p.w3[0] : ((chunk == 1) ? p.w3[1] : p.w3[2]);
      v = w3[kdim*256 + c*16 + u];
    } else {
      v = p.w3[3][kdim*768 + c*48 + u*3 + (chunk - 3)];
    }
    g_W3F[i] = __uint_as_float(cvt_tf32(v));
  }
}

// smem float offsets
constexpr int S_F0  = 0;        // [128][16]  f0; reused as t1 before pair10
constexpr int S_F1  = 2048;     // [128][48]
constexpr int S_EB  = 8192;     // [128][10]
constexpr int S_B11 = 9472;     // [128][27]
constexpr int S_H2  = 12928;    // [128][36] padded rows (tf32 bits)
constexpr int S_W3  = 17536;    // [8192]  fragment-major B tile
constexpr int S_MLPA= 25856;    // 1152
constexpr int S_MLPB= 27008;    // 1152
constexpr int S_TOT = 28160;    // 112640 B (x2 CTA = 225 KB)

__device__ __forceinline__ void radial_half(const float* __restrict__ mlp,
                                            float ei0, float ei1, int mhalf,
                                            float h2[16]) {
  const float* w1 = mlp; const float* b1 = mlp + 64;
  const float* w2 = mlp + 96; const float* b2 = mlp + 1120;
  float h1[32];
#pragma unroll
  for (int j = 0; j < 32; j++)
    h1[j] = fmaxf(fmaf(ei0, w1[j], fmaf(ei1, w1[32 + j], b1[j])), 0.f);
  u64 acc[8];
  const ulonglong2* b2p = reinterpret_cast<const ulonglong2*>(b2 + mhalf);
#pragma unroll
  for (int j = 0; j < 4; j++) {
    ulonglong2 b = b2p[j];
    acc[j*2] = b.x; acc[j*2+1] = b.y;
  }
#pragma unroll
  for (int n = 0; n < 32; n++) {
    u64 h = pk(h1[n]);
    const ulonglong2* wrow = reinterpret_cast<const ulonglong2*>(w2 + n*32 + mhalf);
    ulonglong2 p0 = wrow[0], p1 = wrow[1], p2 = wrow[2], p3 = wrow[3];
    acc[0] = ffma2(h, p0.x, acc[0]); acc[1] = ffma2(h, p0.y, acc[1]);
    acc[2] = ffma2(h, p1.x, acc[2]); acc[3] = ffma2(h, p1.y, acc[3]);
    acc[4] = ffma2(h, p2.x, acc[4]); acc[5] = ffma2(h, p2.y, acc[5]);
    acc[6] = ffma2(h, p3.x, acc[6]); acc[7] = ffma2(h, p3.y, acc[7]);
  }
#pragma unroll
  for (int j = 0; j < 8; j++) {
    float2 q = unpk(acc[j]);
    h2[2*j]   = fmaxf(q.x, 0.f);
    h2[2*j+1] = fmaxf(q.y, 0.f);
  }
}

// Guard-free main kernel: every block covers 128 valid edges.
// Warp tiling: warp w -> edge quarter we = w>>1 (32 edges), n-half wn = w&1.
// Lane (r,q) computes COMPLETE results for edges {ebase+r+8i} x channels {wn*8+2q, +1}.
__global__ void __launch_bounds__(256, 2) convFused(P p) {
  extern __shared__ float sm[];
  int t = threadIdx.x;
  int eb = blockIdx.x * 128;
  int w = t >> 5, lane = t & 31;
  int r = lane >> 2, q = lane & 3;
  int we = w >> 1, wn = w & 1;
  int ebase = we * 32;
  int el2 = t >> 1, mhalf = (t & 1) * 16;
  int c0 = wn*8 + 2*q;               // this lane's first output channel

  // ---------- stage per-edge data ----------
  if (t < 128) {
    int e = eb + t;
    float* EB = sm + S_EB + t*10;
    EB[0] = p.edge_inv[2*e];
    EB[1] = p.edge_inv[2*e+1];
    EB[2] = p.b00[e];
    EB[3] = p.b01[3*e]; EB[4] = p.b01[3*e+1]; EB[5] = p.b01[3*e+2];
    EB[6] = p.b10[3*e]; EB[7] = p.b10[3*e+1]; EB[8] = p.b10[3*e+2];
    reinterpret_cast<int*>(EB)[9] = p.dst[e];
  }
  {
    int half = t & 1;
    int e = eb + el2;
    int s = p.src[e];
    const float4* f0g = reinterpret_cast<const float4*>(p.feat0 + (size_t)s*16);
    float4* f0s = reinterpret_cast<float4*>(sm + S_F0 + el2*16);
    f0s[half*2+0] = f0g[half*2+0];
    f0s[half*2+1] = f0g[half*2+1];
    const float4* f1g = reinterpret_cast<const float4*>(p.feat1 + (size_t)s*48);
    float4* f1s = reinterpret_cast<float4*>(sm + S_F1 + el2*48);
#pragma unroll
    for (int qq = 0; qq < 6; qq++) f1s[half*6+qq] = f1g[half*6+qq];
    const float* bg = p.b11 + (size_t)e*27;
    float* bs = sm + S_B11 + el2*27;
    for (int qq = half; qq < 27; qq += 2) bs[qq] = bg[qq];
  }

  auto stage_mlp = [&](int pr, int off) {
    float* d = sm + off;
    if (t < 64) d[t] = p.w1[pr][t];
    else if (t < 96) d[64 + (t-64)] = p.bb1[pr][t-64];
    else if (t < 128) d[1120 + (t-96)] = p.bb2[pr][t-96];
    for (int i = t; i < 1024; i += 256) d[96 + i] = p.w2[pr][i];
  };
  auto do_radial = [&](int off, bool fold) {
    const float* EB = sm + S_EB + el2*10;
    float h2[16];
    radial_half(sm + off, EB[0], EB[1], mhalf, h2);
    float sc = fold ? EB[2] : 1.f;
#pragma unroll
    for (int j = 0; j < 16; j++)
      sm[S_H2 + el2*36 + mhalf + j] = __uint_as_float(cvt_tf32(h2[j] * sc));
  };
  auto w3load = [&](const float* __restrict__ g, float4 rr[8]) {
    const float4* s4 = reinterpret_cast<const float4*>(g);
#pragma unroll
    for (int qq = 0; qq < 8; qq++) rr[qq] = s4[t + 256*qq];
  };
  auto w3store = [&](const float4 rr[8]) {
    float4* d = reinterpret_cast<float4*>(sm + S_W3);
#pragma unroll
    for (int qq = 0; qq < 8; qq++) d[t + 256*qq] = rr[qq];
  };
  auto w3copy = [&](const float* __restrict__ g) {
    const float4* s4 = reinterpret_cast<const float4*>(g);
    float4* d = reinterpret_cast<float4*>(sm + S_W3);
    float4 rr[8];
#pragma unroll
    for (int qq = 0; qq < 8; qq++) rr[qq] = s4[t + 256*qq];
#pragma unroll
    for (int qq = 0; qq < 8; qq++) d[t + 256*qq] = rr[qq];
  };
  auto loadA2 = [&](uint32_t A0[4][4], uint32_t A1[4][4]) {
    int e0 = ebase + r, e1 = e0 + 8, e2 = e0 + 16, e3 = e0 + 24;
#pragma unroll
    for (int kt = 0; kt < 4; kt++) {
      A0[kt][0] = __float_as_uint(sm[S_H2 + e0*36 + kt*8 + q]);
      A0[kt][1] = __float_as_uint(sm[S_H2 + e1*36 + kt*8 + q]);
      A0[kt][2] = __float_as_uint(sm[S_H2 + e0*36 + kt*8 + q + 4]);
      A0[kt][3] = __float_as_uint(sm[S_H2 + e1*36 + kt*8 + q + 4]);
      A1[kt][0] = __float_as_uint(sm[S_H2 + e2*36 + kt*8 + q]);
      A1[kt][1] = __float_as_uint(sm[S_H2 + e3*36 + kt*8 + q]);
      A1[kt][2] = __float_as_uint(sm[S_H2 + e2*36 + kt*8 + q + 4]);
      A1[kt][3] = __float_as_uint(sm[S_H2 + e3*36 + kt*8 + q + 4]);
    }
  };
  // mma over 2 n-groups (u = 2cl, 2cl+1) for both m-tiles
  auto mma_cl2 = [&](const uint32_t A0[4][4], const uint32_t A1[4][4], int nt0,
                     float D0[2][4], float D1[2][4]) {
#pragma unroll
    for (int i = 0; i < 2; i++)
#pragma unroll
      for (int j = 0; j < 4; j++) { D0[i][j] = 0.f; D1[i][j] = 0.f; }
    const float4* F = reinterpret_cast<const float4*>(sm + S_W3);
    float4 va1 = F[nt0*32 + lane];
    float4 va2 = F[1024 + nt0*32 + lane];
    float4 vb1 = F[(nt0+1)*32 + lane];
    float4 vb2 = F[1024 + (nt0+1)*32 + lane];
    mma_tf32(D0[0], A0[0], __float_as_uint(va1.x), __float_as_uint(va1.y));
    mma_tf32(D0[0], A0[1], __float_as_uint(va1.z), __float_as_uint(va1.w));
    mma_tf32(D0[0], A0[2], __float_as_uint(va2.x), __float_as_uint(va2.y));
    mma_tf32(D0[0], A0[3], __float_as_uint(va2.z), __float_as_uint(va2.w));
    mma_tf32(D0[1], A0[0], __float_as_uint(vb1.x), __float_as_uint(vb1.y));
    mma_tf32(D0[1], A0[1], __float_as_uint(vb1.z), __float_as_uint(vb1.w));
    mma_tf32(D0[1], A0[2], __float_as_uint(vb2.x), __float_as_uint(vb2.y));
    mma_tf32(D0[1], A0[3], __float_as_uint(vb2.z), __float_as_uint(vb2.w));
    mma_tf32(D1[0], A1[0], __float_as_uint(va1.x), __float_as_uint(va1.y));
    mma_tf32(D1[0], A1[1], __float_as_uint(va1.z), __float_as_uint(va1.w));
    mma_tf32(D1[0], A1[2], __float_as_uint(va2.x), __float_as_uint(va2.y));
    mma_tf32(D1[0], A1[3], __float_as_uint(va2.z), __float_as_uint(va2.w));
    mma_tf32(D1[1], A1[0], __float_as_uint(vb1.x), __float_as_uint(vb1.y));
    mma_tf32(D1[1], A1[1], __float_as_uint(vb1.z), __float_as_uint(vb1.w));
    mma_tf32(D1[1], A1[2], __float_as_uint(vb2.x), __float_as_uint(vb2.y));
    mma_tf32(D1[1], A1[3], __float_as_uint(vb2.z), __float_as_uint(vb2.w));
  };

  float o1acc[4][2][3];   // deg-1 accumulator: [edge slot][c low bit][o]

  // pairs 00/01/10: vec-weighted k-contraction; lane finishes (4 edge, 2 c) sums.
  // mode 0 -> direct deg0 atomics; mode 1 -> initialize o1acc with v * b01.
  auto chunk_vec = [&](int mode) {
    uint32_t A0[4][4], A1[4][4];
    loadA2(A0, A1);
    float acc[4][2];
#pragma unroll
    for (int i = 0; i < 4; i++) { acc[i][0] = 0.f; acc[i][1] = 0.f; }
#pragma unroll 1
    for (int cl = 0; cl < 8; cl++) {
      int nt0 = wn*16 + cl*2;
      float D0[2][4], D1[2][4];
      mma_cl2(A0, A1, nt0, D0, D1);
#pragma unroll
      for (int g = 0; g < 2; g++) {
        int u = 2*cl + g;
        float v0 = sm[S_F0 + (ebase + r)*16 + u];
        float v1 = sm[S_F0 + (ebase + 8 + r)*16 + u];
        float v2 = sm[S_F0 + (ebase + 16 + r)*16 + u];
        float v3 = sm[S_F0 + (ebase + 24 + r)*16 + u];
        acc[0][0] = fmaf(D0[g][0], v0, acc[0][0]); acc[0][1] = fmaf(D0[g][1], v0, acc[0][1]);
        acc[1][0] = fmaf(D0[g][2], v1, acc[1][0]); acc[1][1] = fmaf(D0[g][3], v1, acc[1][1]);
        acc[2][0] = fmaf(D1[g][0], v2, acc[2][0]); acc[2][1] = fmaf(D1[g][1], v2, acc[2][1]);
        acc[3][0] = fmaf(D1[g][2], v3, acc[3][0]); acc[3][1] = fmaf(D1[g][3], v3, acc[3][1]);
      }
    }
#pragma unroll
    for (int i = 0; i < 4; i++) {
      int eli = ebase + r + i*8;
      const float* E = sm + S_EB + eli*10;
      int dd = reinterpret_cast<const int*>(E)[9];
      if (mode == 0) {
        atomicAdd(p.out + (size_t)dd*64 + c0*4, acc[i][0]);
        atomicAdd(p.out + (size_t)dd*64 + (c0+1)*4, acc[i][1]);
      } else {
#pragma unroll
        for (int o = 0; o < 3; o++) {
          o1acc[i][0][o] = acc[i][0] * E[3+o];
          o1acc[i][1][o] = acc[i][1] * E[3+o];
        }
      }
    }
  };

  float4 wreg[8];

  stage_mlp(0, S_MLPA);
  __syncthreads();

  // ---- chunk 0: pair00 (b00 folded) -> deg0 ----
  w3load(g_W3F, wreg);
  do_radial(S_MLPA, true);
  w3store(wreg);
  __syncthreads();
  chunk_vec(0);
  stage_mlp(1, S_MLPB);
  w3load(g_W3F + 8192, wreg);
  __syncthreads();

  // ---- chunk 1: pair01 -> o1acc (no atomics) ----
  do_radial(S_MLPB, false);
  w3store(wreg);
  __syncthreads();
  chunk_vec(1);
  stage_mlp(2, S_MLPA);
  w3load(g_W3F + 16384, wreg);
  __syncthreads();

  // ---- chunk 2: pair10 -> deg0; t1 precomputed into S_F0 ----
  do_radial(S_MLPA, false);
  {
    int half = t & 1, kh = half*8;
    const float* EB = sm + S_EB + el2*10;
    float g0 = EB[6], g1 = EB[7], g2 = EB[8];
    const float* f1 = sm + S_F1 + el2*48 + kh*3;
    float* t1 = sm + S_F0 + el2*16 + kh;
#pragma unroll
    for (int j = 0; j < 8; j++)
      t1[j] = f1[j*3]*g0 + f1[j*3+1]*g1 + f1[j*3+2]*g2;
  }
  w3store(wreg);
  __syncthreads();
  chunk_vec(0);
  stage_mlp(3, S_MLPB);
  w3load(g_W3F + 24576, wreg);
  __syncthreads();

  // ---- chunks 3..5: pair11 (f = 0,1,2) -> o1acc; single m-pass, no shfl ----
  do_radial(S_MLPB, false);
  w3store(wreg);
  __syncthreads();
#pragma unroll 1
  for (int f = 0; f < 3; f++) {
    uint32_t A0[4][4], A1[4][4];
    loadA2(A0, A1);
    float s[4][2][3];
#pragma unroll
    for (int i = 0; i < 4; i++)
#pragma unroll
      for (int j1 = 0; j1 < 2; j1++)
#pragma unroll
        for (int k3 = 0; k3 < 3; k3++) s[i][j1][k3] = 0.f;
#pragma unroll 1
    for (int cl = 0; cl < 8; cl++) {
      int nt0 = wn*16 + cl*2;
      float D0[2][4], D1[2][4];
      mma_cl2(A0, A1, nt0, D0, D1);
#pragma unroll
      for (int g = 0; g < 2; g++) {
        int u = 2*cl + g;
#pragma unroll
        for (int i = 0; i < 4; i++) {
          int eli = ebase + r + i*8;
          const float* fp = sm + S_F1 + eli*48 + u*3;
          float fx = fp[0], fy = fp[1], fz = fp[2];
          float d0 = (i < 2) ? D0[g][(i&1)*2]     : D1[g][(i&1)*2];
          float d1 = (i < 2) ? D0[g][(i&1)*2 + 1] : D1[g][(i&1)*2 + 1];
          s[i][0][0] = fmaf(d0, fx, s[i][0][0]);
          s[i][0][1] = fmaf(d0, fy, s[i][0][1]);
          s[i][0][2] = fmaf(d0, fz, s[i][0][2]);
          s[i][1][0] = fmaf(d1, fx, s[i][1][0]);
          s[i][1][1] = fmaf(d1, fy, s[i][1][1]);
          s[i][1][2] = fmaf(d1, fz, s[i][1][2]);
        }
      }
    }
    // apply per-edge basis: o1acc[i][j1][o] += sum_k3 s[i][j1][k3]*B[k3*9 + f*3 + o]
#pragma unroll
    for (int i = 0; i < 4; i++) {
      int eli = ebase + r + i*8;
      const float* B = sm + S_B11 + eli*27 + f*3;
#pragma unroll
      for (int j1 = 0; j1 < 2; j1++) {
        float s0 = s[i][j1][0], s1 = s[i][j1][1], s2 = s[i][j1][2];
        o1acc[i][j1][0] += s0*B[0] + s1*B[9]  + s2*B[18];
        o1acc[i][j1][1] += s0*B[1] + s1*B[10] + s2*B[19];
        o1acc[i][j1][2] += s0*B[2] + s1*B[11] + s2*B[20];
      }
    }
    if (f < 2) {
      __syncthreads();
      w3copy(g_W3F + (4 + f)*8192);
      __syncthreads();
    }
  }

  // ---- flush deg-1 accumulator: 24 REDG per thread-owned (4 edge x 2 c) ----
#pragma unroll
  for (int i = 0; i < 4; i++) {
    int eli = ebase + r + i*8;
    int dd = reinterpret_cast<const int*>(sm + S_EB + eli*10)[9];
    float* ob = p.out + (size_t)dd*64;
#pragma unroll
    for (int j1 = 0; j1 < 2; j1++) {
      int c = c0 + j1;
      atomicAdd(ob + c*4 + 1, o1acc[i][j1][0]);
      atomicAdd(ob + c*4 + 2, o1acc[i][j1][1]);
      atomicAdd(ob + c*4 + 3, o1acc[i][j1][2]);
    }
  }
}

// ---------- scalar tail (E % 128 edges; weights from gmem) ----------
__device__ void radial_g(const float* w1, const float* b1, const float* w2,
                         const float* b2, float ei0, float ei1, float h2[32]) {
  float h1[32];
  for (int m = 0; m < 32; m++)
    h1[m] = fmaxf(fmaf(ei0, w1[m], fmaf(ei1, w1[32+m], b1[m])), 0.f);
  for (int m = 0; m < 32; m++) {
    float a = b2[m];
    for (int n = 0; n < 32; n++) a = fmaf(h1[n], w2[n*32 + m], a);
    h2[m] = fmaxf(a, 0.f);
  }
}

__global__ void convTail(P p, int e0) {
  int e = e0 + threadIdx.x;
  if (e >= p.E) return;
  int s = p.src[e], d = p.dst[e];
  float ei0 = p.edge_inv[2*e], ei1 = p.edge_inv[2*e+1];
  float f0[16], f1[48];
  for (int i = 0; i < 16; i++) f0[i] = p.feat0[(size_t)s*16 + i];
  for (int i = 0; i < 48; i++) f1[i] = p.feat1[(size_t)s*48 + i];
  float h2[32], out0[16], o1[48];
  for (int c = 0; c < 16; c++) out0[c] = 0.f;
  for (int j = 0; j < 48; j++) o1[j] = 0.f;
  radial_g(p.w1[0], p.bb1[0], p.w2[0], p.bb2[0], ei0, ei1, h2);
  float bv = p.b00[e];
  for (int c = 0; c < 16; c++) {
    float v = 0.f;
    for (int k = 0; k < 16; k++) {
      float rw = 0.f;
      for (int m = 0; m < 32; m++) rw = fmaf(h2[m], p.w3[0][m*256 + c*16 + k], rw);
      v = fmaf(rw, f0[k], v);
    }
    out0[c] += v * bv;
  }
  radial_g(p.w1[1], p.bb1[1], p.w2[1], p.bb2[1], ei0, ei1, h2);
  float q0 = p.b01[e*3], q1 = p.b01[e*3+1], q2 = p.b01[e*3+2];
  for (int c = 0; c < 16; c++) {
    float v = 0.f;
    for (int k = 0; k < 16; k++) {
      float rw = 0.f;
      for (int m = 0; m < 32; m++) rw = fmaf(h2[m], p.w3[1][m*256 + c*16 + k], rw);
      v = fmaf(rw, f0[k], v);
    }
    o1[c*3] += v*q0; o1[c*3+1] += v*q1; o1[c*3+2] += v*q2;
  }
  radial_g(p.w1[2], p.bb1[2], p.w2[2], p.bb2[2], ei0, ei1, h2);
  float g0 = p.b10[e*3], g1 = p.b10[e*3+1], g2 = p.b10[e*3+2];
  for (int c = 0; c < 16; c++) {
    float v = 0.f;
    for (int k = 0; k < 16; k++) {
      float rw = 0.f;
      for (int m = 0; m < 32; m++) rw = fmaf(h2[m], p.w3[2][m*256 + c*16 + k], rw);
      v = fmaf(rw, f1[k*3]*g0 + f1[k*3+1]*g1 + f1[k*3+2]*g2, v);
    }
    out0[c] += v;
  }
  radial_g(p.w1[3], p.bb1[3], p.w2[3], p.bb2[3], ei0, ei1, h2);
  for (int c = 0; c < 16; c++) {
    for (int k = 0; k < 16; k++) {
      for (int f = 0; f < 3; f++) {
        float rw = 0.f;
        for (int m = 0; m < 32; m++) rw = fmaf(h2[m], p.w3[3][m*768 + c*48 + k*3 + f], rw);
        for (int o = 0; o < 3; o++) {
          float tt = f1[k*3]*p.b11[(size_t)e*27 + f*3 + o]
                   + f1[k*3+1]*p.b11[(size_t)e*27 + 9 + f*3 + o]
                   + f1[k*3+2]*p.b11[(size_t)e*27 + 18 + f*3 + o];
          o1[c*3+o] = fmaf(rw, tt, o1[c*3+o]);
        }
      }
    }
  }
  float* outp = p.out + (size_t)d * 64;
  for (int c = 0; c < 16; c++) {
    atomicAdd(outp + c*4,     out0[c]);
    atomicAdd(outp + c*4 + 1, o1[c*3]);
    atomicAdd(outp + c*4 + 2, o1[c*3+1]);
    atomicAdd(outp + c*4 + 3, o1[c*3+2]);
  }
}

}  // namespace

extern "C" void kernel_launch(void* const* d_in, const int* in_sizes, int n_in,
                              void* d_out, int out_size) {
  P p{};
  p.feat0    = (const float*)d_in[0];
  p.feat1    = (const float*)d_in[1];
  p.edge_inv = (const float*)d_in[2];
  p.src      = (const int*)d_in[3];
  p.dst      = (const int*)d_in[4];
  p.b00 = (const float*)d_in[5];
  p.b01 = (const float*)d_in[6];
  p.b10 = (const float*)d_in[7];
  p.b11 = (const float*)d_in[8];
  const int base[4] = {9, 14, 19, 24};   // 00, 01, 10, 11
  for (int pr = 0; pr < 4; pr++) {
    p.w1[pr]  = (const float*)d_in[base[pr]];
    p.bb1[pr] = (const float*)d_in[base[pr]+1];
    p.w2[pr]  = (const float*)d_in[base[pr]+2];
    p.bb2[pr] = (const float*)d_in[base[pr]+3];
    p.w3[pr]  = (const float*)d_in[base[pr]+4];
  }
  p.out = (float*)d_out;
  p.E = in_sizes[3];

  static bool attr_done = false;
  if (!attr_done) {
    cudaFuncSetAttribute(convFused, cudaFuncAttributeMaxDynamicSharedMemorySize,
                         S_TOT * 4);
    attr_done = true;
  }

  int nblk = (out_size + 255) / 256;
  if (nblk < 192) nblk = 192;
  prolog<<<nblk, 256>>>(p, out_size);

  int nfull = p.E / 128;
  if (nfull > 0) convFused<<<nfull, 256, S_TOT * 4>>>(p);
  int tail = p.E - nfull * 128;
  if (tail > 0) convTail<<<1, tail>>>(p, nfull * 128);
}